// round 1
// baseline (speedup 1.0000x reference)
#include <cuda_runtime.h>
#include <cstdint>

#define BSZ    16384
#define NHEAD  8
#define DKV    32
#define DMODEL 256      // H*DV
#define NMOD   3
#define QKV_LD 768      // NMOD * DMODEL
#define NROWS  (BSZ*NMOD)
#define LN_EPS 1e-6f
// TEMP = sqrt(32)
#define TEMP_INV 0.17677669529663687f

// ---------------- scratch (static device allocations; no cudaMalloc) --------
__device__ float g_q[BSZ*QKV_LD];
__device__ float g_k[BSZ*QKV_LD];
__device__ float g_v[BSZ*QKV_LD];
__device__ float g_o[BSZ*QKV_LD];
__device__ float g_fc[BSZ*QKV_LD];
__device__ float g_x[BSZ*QKV_LD];
__device__ float g_logits[BSZ*NHEAD*9];
__device__ unsigned g_minkey;

// -------- float ordering key for atomic min over signed floats --------------
__device__ __forceinline__ unsigned f2key(float f) {
    unsigned u = __float_as_uint(f);
    return (u & 0x80000000u) ? ~u : (u | 0x80000000u);
}
__device__ __forceinline__ float key2f(unsigned k) {
    unsigned u = (k & 0x80000000u) ? (k & 0x7FFFFFFFu) : ~k;
    return __uint_as_float(u);
}

__global__ void init_min_kernel() { g_minkey = 0xFFFFFFFFu; }

// ---------------- classic 128x128x8 SGEMM, 8x8 per thread -------------------
// C[M, 256] = A[M, K] (lda) @ W[K, 256] + bias, written with ldc.
// Requires M % 128 == 0. N fixed at 256 (grid.x == 2).
__device__ __forceinline__ void sgemm_tile(
    const float* __restrict__ A, int lda, int K,
    const float* __restrict__ W, const float* __restrict__ bias,
    float* __restrict__ C, int ldc)
{
    __shared__ __align__(16) float As[8][128];
    __shared__ __align__(16) float Bs[8][128];

    const int tid  = threadIdx.x;
    const int tx   = tid & 15;          // 0..15 (col groups of 8)
    const int ty   = tid >> 4;          // 0..15 (row groups of 8)
    const int row0 = blockIdx.y * 128;
    const int col0 = blockIdx.x * 128;

    const int ar = tid >> 1;            // A tile row 0..127
    const int ak = (tid & 1) * 4;       // A tile k base {0,4}
    const int bk = tid >> 5;            // B tile k 0..7
    const int bn = (tid & 31) * 4;      // B tile col base

    float acc[8][8];
#pragma unroll
    for (int i = 0; i < 8; i++)
#pragma unroll
        for (int j = 0; j < 8; j++) acc[i][j] = 0.f;

    const float* Arow = A + (long)(row0 + ar) * lda;

    for (int k0 = 0; k0 < K; k0 += 8) {
#pragma unroll
        for (int i = 0; i < 4; i++) {
            int kk = k0 + ak + i;
            As[ak + i][ar] = (kk < K) ? Arow[kk] : 0.f;
        }
        {
            int kk = k0 + bk;
            float4 bv = make_float4(0.f, 0.f, 0.f, 0.f);
            if (kk < K) bv = *(const float4*)(W + (long)kk * 256 + col0 + bn);
            *(float4*)&Bs[bk][bn] = bv;
        }
        __syncthreads();
#pragma unroll
        for (int k = 0; k < 8; k++) {
            float4 a0 = *(const float4*)&As[k][ty * 8];
            float4 a1 = *(const float4*)&As[k][ty * 8 + 4];
            float4 b0 = *(const float4*)&Bs[k][tx * 8];
            float4 b1 = *(const float4*)&Bs[k][tx * 8 + 4];
            float a[8] = {a0.x, a0.y, a0.z, a0.w, a1.x, a1.y, a1.z, a1.w};
            float b[8] = {b0.x, b0.y, b0.z, b0.w, b1.x, b1.y, b1.z, b1.w};
#pragma unroll
            for (int i = 0; i < 8; i++)
#pragma unroll
                for (int j = 0; j < 8; j++) acc[i][j] = fmaf(a[i], b[j], acc[i][j]);
        }
        __syncthreads();
    }

#pragma unroll
    for (int i = 0; i < 8; i++) {
        int r = row0 + ty * 8 + i;
#pragma unroll
        for (int j = 0; j < 8; j += 4) {
            int c = col0 + tx * 8 + j;
            float4 o;
            o.x = acc[i][j + 0] + bias[c + 0];
            o.y = acc[i][j + 1] + bias[c + 1];
            o.z = acc[i][j + 2] + bias[c + 2];
            o.w = acc[i][j + 3] + bias[c + 3];
            *(float4*)(C + (long)r * ldc + c) = o;
        }
    }
}

struct QKVArgs {
    const float* W[9];   // z = t*3 + m ; t: 0=q 1=k 2=v
    const float* Bi[9];
};

__global__ void __launch_bounds__(256) sgemm_qkv_kernel(
    const float* __restrict__ X, QKVArgs args)
{
    int z = blockIdx.z;
    int t = z / 3, m = z - t * 3;
    const int offs[4] = {0, 2000, 2500, 2900};
    int K = offs[m + 1] - offs[m];
    const float* A = X + offs[m];
    float* base = (t == 0) ? g_q : (t == 1) ? g_k : g_v;
    sgemm_tile(A, 2900, K, args.W[z], args.Bi[z], base + m * DMODEL, QKV_LD);
}

__global__ void __launch_bounds__(256) sgemm_fc_kernel(
    const float* __restrict__ fc_w, const float* __restrict__ fc_b)
{
    sgemm_tile(g_o, DMODEL, DMODEL, fc_w, fc_b, g_fc, DMODEL);
}

// ------------- attention logits + global min --------------------------------
__global__ void __launch_bounds__(256) attn_logits_kernel()
{
    int t  = blockIdx.x * blockDim.x + threadIdx.x;   // exactly BS*H threads
    int bs = t >> 3, h = t & 7;

    const float4* qb = (const float4*)(g_q + bs * QKV_LD + h * DKV);
    const float4* kb = (const float4*)(g_k + bs * QKV_LD + h * DKV);

    float4 kr[3][8];
#pragma unroll
    for (int n = 0; n < 3; n++)
#pragma unroll
        for (int j = 0; j < 8; j++) kr[n][j] = kb[n * 64 + j];

    float lmin = 3.4e38f;
#pragma unroll
    for (int m = 0; m < 3; m++) {
        float4 qv[8];
#pragma unroll
        for (int j = 0; j < 8; j++) qv[j] = qb[m * 64 + j];
#pragma unroll
        for (int n = 0; n < 3; n++) {
            float s = 0.f;
#pragma unroll
            for (int j = 0; j < 8; j++) {
                s = fmaf(qv[j].x, kr[n][j].x, s);
                s = fmaf(qv[j].y, kr[n][j].y, s);
                s = fmaf(qv[j].z, kr[n][j].z, s);
                s = fmaf(qv[j].w, kr[n][j].w, s);
            }
            s *= TEMP_INV;
            g_logits[t * 9 + m * 3 + n] = s;
            lmin = fminf(lmin, s);
        }
    }
    // warp-reduce min, then one atomic per warp
#pragma unroll
    for (int off = 16; off; off >>= 1)
        lmin = fminf(lmin, __shfl_xor_sync(0xFFFFFFFFu, lmin, off));
    if ((threadIdx.x & 31) == 0) atomicMin(&g_minkey, f2key(lmin));
}

// ------------- scale / L1 / softmax / PV ------------------------------------
__global__ void __launch_bounds__(256) attn_softmax_o_kernel()
{
    int t  = blockIdx.x * blockDim.x + threadIdx.x;
    int bs = t >> 3, h = t & 7;

    float gabs = fabsf(key2f(g_minkey));
    float inv  = 1.0f / gabs;

    const float* lg = g_logits + t * 9;
    const float4* vb = (const float4*)(g_v + bs * QKV_LD + h * DKV);
    float* ob = g_o + bs * QKV_LD + h * DKV;

#pragma unroll
    for (int m = 0; m < 3; m++) {
        float r0 = lg[m * 3 + 0] * inv;
        float r1 = lg[m * 3 + 1] * inv;
        float r2 = lg[m * 3 + 2] * inv;
        float l1 = fmaxf(fabsf(r0) + fabsf(r1) + fabsf(r2), 1e-12f);
        r0 /= l1; r1 /= l1; r2 /= l1;
        float mx = fmaxf(r0, fmaxf(r1, r2));
        float e0 = expf(r0 - mx), e1 = expf(r1 - mx), e2 = expf(r2 - mx);
        float es = e0 + e1 + e2;
        float p0 = e0 / es, p1 = e1 / es, p2 = e2 / es;

        float4* o4 = (float4*)(ob + m * DMODEL);
#pragma unroll
        for (int j = 0; j < 8; j++) {
            float4 v0 = vb[j], v1 = vb[64 + j], v2 = vb[128 + j];
            float4 r;
            r.x = p0 * v0.x + p1 * v1.x + p2 * v2.x;
            r.y = p0 * v0.y + p1 * v1.y + p2 * v2.y;
            r.z = p0 * v0.z + p1 * v1.z + p2 * v2.z;
            r.w = p0 * v0.w + p1 * v1.w + p2 * v2.w;
            o4[j] = r;
        }
    }
}

// ------------- residual + layernorm ------------------------------------------
__global__ void __launch_bounds__(256) ln_kernel(
    const float* __restrict__ ln_g, const float* __restrict__ ln_b)
{
    int row  = blockIdx.x * 8 + (threadIdx.x >> 5);   // one warp per row
    int lane = threadIdx.x & 31;
    const float* fr = g_fc + (long)row * DMODEL;       // already includes fc_b
    const float* vr = g_v  + (long)row * DMODEL;       // residual = v

    float x[8];
#pragma unroll
    for (int i = 0; i < 8; i++) x[i] = fr[lane + i * 32] + vr[lane + i * 32];

    float s = 0.f;
#pragma unroll
    for (int i = 0; i < 8; i++) s += x[i];
#pragma unroll
    for (int off = 16; off; off >>= 1) s += __shfl_xor_sync(0xFFFFFFFFu, s, off);
    float mu = s * (1.0f / 256.0f);

    float ss = 0.f;
#pragma unroll
    for (int i = 0; i < 8; i++) { float d = x[i] - mu; ss += d * d; }
#pragma unroll
    for (int off = 16; off; off >>= 1) ss += __shfl_xor_sync(0xFFFFFFFFu, ss, off);
    float rstd = rsqrtf(ss * (1.0f / 256.0f) + LN_EPS);

    float* xr = g_x + (long)row * DMODEL;
#pragma unroll
    for (int i = 0; i < 8; i++) {
        int idx = lane + i * 32;
        xr[idx] = (x[i] - mu) * rstd * ln_g[idx] + ln_b[idx];
    }
}

// ------------- final skinny GEMM [BS,768] @ [768,5] --------------------------
__global__ void __launch_bounds__(256) out_kernel(
    const float* __restrict__ out_w, const float* __restrict__ out_b,
    float* __restrict__ out)
{
    __shared__ float sw[768 * 5];
    for (int i = threadIdx.x; i < 768 * 5; i += 256) sw[i] = out_w[i];
    __syncthreads();

    int samp = blockIdx.x * 8 + (threadIdx.x >> 5);   // one warp per sample
    int lane = threadIdx.x & 31;
    const float* xr = g_x + (long)samp * 768;

    float acc[5] = {0.f, 0.f, 0.f, 0.f, 0.f};
    for (int i = lane; i < 768; i += 32) {
        float xv = xr[i];
#pragma unroll
        for (int c = 0; c < 5; c++) acc[c] = fmaf(xv, sw[i * 5 + c], acc[c]);
    }
#pragma unroll
    for (int off = 16; off; off >>= 1)
#pragma unroll
        for (int c = 0; c < 5; c++)
            acc[c] += __shfl_xor_sync(0xFFFFFFFFu, acc[c], off);

    if (lane < 5) out[samp * 5 + lane] = acc[lane] + out_b[lane];
}

// =============================================================================
extern "C" void kernel_launch(void* const* d_in, const int* in_sizes, int n_in,
                              void* d_out, int out_size)
{
    const float* X = (const float*)d_in[0];
    QKVArgs args;
    // q: wq0,bq0,wq1,bq1,wq2,bq2 = d_in[1..6]; k: 7..12; v: 13..18
    for (int t = 0; t < 3; t++)
        for (int m = 0; m < 3; m++) {
            args.W [t * 3 + m] = (const float*)d_in[1 + t * 6 + m * 2];
            args.Bi[t * 3 + m] = (const float*)d_in[2 + t * 6 + m * 2];
        }
    const float* fc_w  = (const float*)d_in[19];
    const float* fc_b  = (const float*)d_in[20];
    const float* ln_g  = (const float*)d_in[21];
    const float* ln_b  = (const float*)d_in[22];
    const float* out_w = (const float*)d_in[23];
    const float* out_b = (const float*)d_in[24];
    float* out = (float*)d_out;

    init_min_kernel<<<1, 1>>>();

    dim3 gq(2, BSZ / 128, 9);
    sgemm_qkv_kernel<<<gq, 256>>>(X, args);

    attn_logits_kernel<<<(BSZ * NHEAD) / 256, 256>>>();
    attn_softmax_o_kernel<<<(BSZ * NHEAD) / 256, 256>>>();

    dim3 gf(2, NROWS / 128, 1);
    sgemm_fc_kernel<<<gf, 256>>>(fc_w, fc_b);

    ln_kernel<<<NROWS / 8, 256>>>(ln_g, ln_b);
    out_kernel<<<BSZ / 8, 256>>>(out_w, out_b, out);
}

// round 3
// speedup vs baseline: 1.9882x; 1.9882x over previous
#include <cuda_runtime.h>
#include <cuda_bf16.h>
#include <cstdint>

#define BSZ    16384
#define QKV_LD 768
#define NROWS  (BSZ*3)
#define LN_EPS 1e-6f
#define TEMP_INV 0.17677669529663687f
#define APAD   3072      // padded concat K: 2048 + 512 + 512

// ---------------- scratch (static device arrays; no cudaMalloc) --------------
__device__ __align__(16) float g_q [BSZ*QKV_LD];
__device__ __align__(16) float g_k [BSZ*QKV_LD];
__device__ __align__(16) float g_v [BSZ*QKV_LD];
__device__ __align__(16) float g_o [BSZ*QKV_LD];
__device__ __align__(16) float g_fc[BSZ*QKV_LD];
__device__ __align__(16) float g_x [BSZ*QKV_LD];
__device__ __align__(16) float g_logits[BSZ*8*9];
__device__ unsigned g_minkey;

__device__ __align__(16) __nv_bfloat16 g_ah[(size_t)BSZ*APAD];
__device__ __align__(16) __nv_bfloat16 g_al[(size_t)BSZ*APAD];
__device__ __align__(16) __nv_bfloat16 g_wh[(size_t)3*256*APAD];
__device__ __align__(16) __nv_bfloat16 g_wl[(size_t)3*256*APAD];
__device__ __align__(16) __nv_bfloat16 g_oh[(size_t)NROWS*256];
__device__ __align__(16) __nv_bfloat16 g_ol[(size_t)NROWS*256];
__device__ __align__(16) __nv_bfloat16 g_fch[256*256];
__device__ __align__(16) __nv_bfloat16 g_fcl[256*256];

// ---------------- small helpers ----------------------------------------------
__device__ __forceinline__ unsigned f2key(float f) {
    unsigned u = __float_as_uint(f);
    return (u & 0x80000000u) ? ~u : (u | 0x80000000u);
}
__device__ __forceinline__ float key2f(unsigned k) {
    unsigned u = (k & 0x80000000u) ? (k & 0x7FFFFFFFu) : ~k;
    return __uint_as_float(u);
}
__global__ void init_min_kernel() { g_minkey = 0xFFFFFFFFu; }

__device__ __forceinline__ uint32_t su32(const void* p) {
    return (uint32_t)__cvta_generic_to_shared(p);
}
__device__ __forceinline__ void cp16(uint32_t dst, const void* src) {
    asm volatile("cp.async.cg.shared.global [%0], [%1], 16;"
                 :: "r"(dst), "l"(src) : "memory");
}
__device__ __forceinline__ void cp_commit() {
    asm volatile("cp.async.commit_group;" ::: "memory");
}
__device__ __forceinline__ void ldm_x4(uint32_t& r0, uint32_t& r1, uint32_t& r2,
                                       uint32_t& r3, uint32_t addr) {
    asm volatile("ldmatrix.sync.aligned.m8n8.x4.shared.b16 {%0,%1,%2,%3}, [%4];"
                 : "=r"(r0), "=r"(r1), "=r"(r2), "=r"(r3) : "r"(addr));
}
__device__ __forceinline__ void mma_bf16(float* c, uint32_t a0, uint32_t a1,
                                         uint32_t a2, uint32_t a3,
                                         uint32_t b0, uint32_t b1) {
    asm volatile(
        "mma.sync.aligned.m16n8k16.row.col.f32.bf16.bf16.f32 "
        "{%0,%1,%2,%3}, {%4,%5,%6,%7}, {%8,%9}, {%0,%1,%2,%3};"
        : "+f"(c[0]), "+f"(c[1]), "+f"(c[2]), "+f"(c[3])
        : "r"(a0), "r"(a1), "r"(a2), "r"(a3), "r"(b0), "r"(b1));
}
__device__ __forceinline__ void split_bf16(float v, __nv_bfloat16& h, __nv_bfloat16& l) {
    h = __float2bfloat16(v);
    l = __float2bfloat16(v - __bfloat162float(h));
}

// ---------------- conversion kernels -----------------------------------------
__global__ void __launch_bounds__(256) conv_x_kernel(const float* __restrict__ X)
{
    int col2 = (blockIdx.x * 256 + threadIdx.x) * 2;
    int row  = blockIdx.y;
    __nv_bfloat16 h[2], l[2];
#pragma unroll
    for (int e = 0; e < 2; e++) {
        int col = col2 + e;
        float x = 0.f;
        if (col < 2048)      { if (col < 2000) x = X[(size_t)row*2900 + col]; }
        else if (col < 2560) { int c = col-2048; if (c < 500) x = X[(size_t)row*2900 + 2000 + c]; }
        else                 { int c = col-2560; if (c < 400) x = X[(size_t)row*2900 + 2500 + c]; }
        split_bf16(x, h[e], l[e]);
    }
    __nv_bfloat162 hh; hh.x = h[0]; hh.y = h[1];
    __nv_bfloat162 ll; ll.x = l[0]; ll.y = l[1];
    *(__nv_bfloat162*)&g_ah[(size_t)row*APAD + col2] = hh;
    *(__nv_bfloat162*)&g_al[(size_t)row*APAD + col2] = ll;
}

struct W9 { const float* w[9]; };
__global__ void __launch_bounds__(256) conv_w_kernel(W9 ws)
{
    const int Km[3]   = {2000, 500, 400};
    const int Kp[3]   = {2048, 512, 512};
    const int colA[3] = {0, 2048, 2560};
    int z = blockIdx.z, t = z / 3, m = z - t * 3;
    int idx = (blockIdx.x * 256 + threadIdx.x) * 2;
    if (idx >= 256 * Kp[m]) return;
    int n  = idx / Kp[m];
    int kp = idx - n * Kp[m];
    const float* W = ws.w[z];
    float x0 = (kp     < Km[m]) ? W[(size_t)kp*256 + n]     : 0.f;
    float x1 = (kp + 1 < Km[m]) ? W[(size_t)(kp+1)*256 + n] : 0.f;
    __nv_bfloat16 h0, l0, h1, l1;
    split_bf16(x0, h0, l0); split_bf16(x1, h1, l1);
    size_t o = (size_t)t*256*APAD + (size_t)n*APAD + colA[m] + kp;
    __nv_bfloat162 hh; hh.x = h0; hh.y = h1;
    __nv_bfloat162 ll; ll.x = l0; ll.y = l1;
    *(__nv_bfloat162*)&g_wh[o] = hh;
    *(__nv_bfloat162*)&g_wl[o] = ll;
}

__global__ void __launch_bounds__(256) conv_fcw_kernel(const float* __restrict__ fcw)
{
    int idx = (blockIdx.x * 256 + threadIdx.x) * 2;
    int n = idx >> 8, k = idx & 255;
    float x0 = fcw[(size_t)k*256 + n];
    float x1 = fcw[(size_t)(k+1)*256 + n];
    __nv_bfloat16 h0, l0, h1, l1;
    split_bf16(x0, h0, l0); split_bf16(x1, h1, l1);
    __nv_bfloat162 hh; hh.x = h0; hh.y = h1;
    __nv_bfloat162 ll; ll.x = l0; ll.y = l1;
    *(__nv_bfloat162*)&g_fch[n*256 + k] = hh;
    *(__nv_bfloat162*)&g_fcl[n*256 + k] = ll;
}

__global__ void __launch_bounds__(256) conv_o_kernel()
{
    size_t i2 = ((size_t)blockIdx.x * 256 + threadIdx.x) * 2;
    float2 v = *(const float2*)&g_o[i2];
    __nv_bfloat16 h0, l0, h1, l1;
    split_bf16(v.x, h0, l0); split_bf16(v.y, h1, l1);
    __nv_bfloat162 hh; hh.x = h0; hh.y = h1;
    __nv_bfloat162 ll; ll.x = l0; ll.y = l1;
    *(__nv_bfloat162*)&g_oh[i2] = hh;
    *(__nv_bfloat162*)&g_ol[i2] = ll;
}

// ---------------- mma.sync split-bf16 GEMM -------------------------------------
// C[M,256] = (Ah+Al)[M,K] @ (Bh+Bl)[K,256]^T-form + bias
//          ~= Ah@Bh + Al@Bh + Ah@Bl  (virtual K = 3*Kp, segmented)
// A: [rows, ldA] bf16 (row-major K), B: [256, ldB] bf16 (row n holds K values)
struct GP {
    const __nv_bfloat16 *Ah, *Al, *Bh, *Bl;
    int ldA, ldB, colA, colB, Kp, lg;     // lg = log2(Kp/32)
    const float* bias;
    float* C; int ldc;
};

// smem: 3 stages, A[128][40] + B[128][40] bf16 per stage (80B row stride)
#define SSTG 10240
#define SMEM_GEMM (6*SSTG)

__device__ __forceinline__ void gemm_body(const GP p)
{
    extern __shared__ __align__(16) char dsm[];
    const int tid  = threadIdx.x;
    const int lane = tid & 31, wid = tid >> 5;
    const int wm = wid >> 2, wn = wid & 3;            // 2x4 warp grid
    const int row0 = blockIdx.y * 128, col0 = blockIdx.x * 128;
    const uint32_t sbase = su32(dsm);

    const int ck = p.Kp >> 5;          // chunks of K=32 per segment
    const int nchunk = 3 * ck;

    auto load_chunk = [&](int c) {
        int seg = c >> p.lg;
        int kc  = c & (ck - 1);
        const __nv_bfloat16* A = (seg == 1) ? p.Al : p.Ah;
        const __nv_bfloat16* B = (seg == 2) ? p.Bl : p.Bh;
        const __nv_bfloat16* As = A + (size_t)row0 * p.ldA + p.colA + kc * 32;
        const __nv_bfloat16* Bs = B + (size_t)col0 * p.ldB + p.colB + kc * 32;
        int st = c % 3;
        uint32_t Ad = sbase + st * SSTG;
        uint32_t Bd = sbase + 3 * SSTG + st * SSTG;
#pragma unroll
        for (int i = 0; i < 2; i++) {
            int id = tid + i * 256, r = id >> 2, kg = id & 3;
            cp16(Ad + r * 80 + kg * 16, As + (size_t)r * p.ldA + kg * 8);
        }
#pragma unroll
        for (int i = 0; i < 2; i++) {
            int id = tid + i * 256, n = id >> 2, kg = id & 3;
            cp16(Bd + n * 80 + kg * 16, Bs + (size_t)n * p.ldB + kg * 8);
        }
    };

    float acc[4][4][4];
#pragma unroll
    for (int i = 0; i < 4; i++)
#pragma unroll
        for (int j = 0; j < 4; j++)
#pragma unroll
            for (int r = 0; r < 4; r++) acc[i][j][r] = 0.f;

    load_chunk(0); cp_commit();
    load_chunk(1); cp_commit();

    // per-lane ldmatrix byte offsets (80B smem row stride)
    const uint32_t a_off = (uint32_t)((wm * 64 + (lane & 15)) * 80 + ((lane >> 4) << 4));
    const uint32_t b_off = (uint32_t)((wn * 32 + (lane & 7) + ((lane & 16) >> 1)) * 80
                                      + ((lane & 8) << 1));

    for (int c = 0; c < nchunk; c++) {
        if (c + 2 < nchunk) load_chunk(c + 2);
        cp_commit();
        asm volatile("cp.async.wait_group 2;" ::: "memory");
        __syncthreads();
        const uint32_t Ab = sbase + (c % 3) * SSTG + a_off;
        const uint32_t Bb = sbase + 3 * SSTG + (c % 3) * SSTG + b_off;
#pragma unroll
        for (int kk = 0; kk < 64; kk += 32) {         // kk in bytes: k=0,16
            uint32_t a[4][4], b[2][4];
#pragma unroll
            for (int mt = 0; mt < 4; mt++)
                ldm_x4(a[mt][0], a[mt][1], a[mt][2], a[mt][3],
                       Ab + mt * 16 * 80 + kk);
#pragma unroll
            for (int ng = 0; ng < 2; ng++)
                ldm_x4(b[ng][0], b[ng][1], b[ng][2], b[ng][3],
                       Bb + ng * 16 * 80 + kk);
#pragma unroll
            for (int mt = 0; mt < 4; mt++)
#pragma unroll
                for (int nt = 0; nt < 4; nt++)
                    mma_bf16(acc[mt][nt],
                             a[mt][0], a[mt][1], a[mt][2], a[mt][3],
                             b[nt >> 1][(nt & 1) * 2], b[nt >> 1][(nt & 1) * 2 + 1]);
        }
        __syncthreads();
    }

    // epilogue
    const int grp = lane >> 2, tig = lane & 3;
#pragma unroll
    for (int mt = 0; mt < 4; mt++) {
        int r = row0 + wm * 64 + mt * 16 + grp;
#pragma unroll
        for (int nt = 0; nt < 4; nt++) {
            int col = col0 + wn * 32 + nt * 8 + tig * 2;
            float b0 = p.bias[col], b1 = p.bias[col + 1];
            float2 lo, hi;
            lo.x = acc[mt][nt][0] + b0; lo.y = acc[mt][nt][1] + b1;
            hi.x = acc[mt][nt][2] + b0; hi.y = acc[mt][nt][3] + b1;
            *(float2*)(p.C + (size_t)r * p.ldc + col) = lo;
            *(float2*)(p.C + (size_t)(r + 8) * p.ldc + col) = hi;
        }
    }
}

struct B9 { const float* b[9]; };

__global__ void __launch_bounds__(256) qkv_gemm_kernel(B9 biases)
{
    const int colA[3] = {0, 2048, 2560};
    const int Kp[3]   = {2048, 512, 512};
    const int lg[3]   = {6, 4, 4};      // log2(Kp/32)
    int z = blockIdx.z, t = z / 3, m = z - t * 3;
    GP p;
    p.Ah = g_ah; p.Al = g_al; p.ldA = APAD; p.colA = colA[m];
    p.Bh = g_wh + (size_t)t * 256 * APAD;
    p.Bl = g_wl + (size_t)t * 256 * APAD;
    p.ldB = APAD; p.colB = colA[m];
    p.Kp = Kp[m]; p.lg = lg[m];
    p.bias = biases.b[z];
    p.C = ((t == 0) ? g_q : (t == 1) ? g_k : g_v) + m * 256;
    p.ldc = QKV_LD;
    gemm_body(p);
}

__global__ void __launch_bounds__(256) fc_gemm_kernel(const float* fc_b)
{
    GP p;
    p.Ah = g_oh; p.Al = g_ol; p.ldA = 256; p.colA = 0;
    p.Bh = g_fch; p.Bl = g_fcl; p.ldB = 256; p.colB = 0;
    p.Kp = 256; p.lg = 3;
    p.bias = fc_b; p.C = g_fc; p.ldc = 256;
    gemm_body(p);
}

// ------------- attention logits + global min ---------------------------------
__global__ void __launch_bounds__(256) attn_logits_kernel()
{
    int t  = blockIdx.x * blockDim.x + threadIdx.x;
    int bs = t >> 3, h = t & 7;
    const float4* qb = (const float4*)(g_q + bs * QKV_LD + h * 32);
    const float4* kb = (const float4*)(g_k + bs * QKV_LD + h * 32);

    float4 kr[3][8];
#pragma unroll
    for (int n = 0; n < 3; n++)
#pragma unroll
        for (int j = 0; j < 8; j++) kr[n][j] = kb[n * 64 + j];

    float lmin = 3.4e38f;
#pragma unroll
    for (int m = 0; m < 3; m++) {
        float4 qv[8];
#pragma unroll
        for (int j = 0; j < 8; j++) qv[j] = qb[m * 64 + j];
#pragma unroll
        for (int n = 0; n < 3; n++) {
            float s = 0.f;
#pragma unroll
            for (int j = 0; j < 8; j++) {
                s = fmaf(qv[j].x, kr[n][j].x, s);
                s = fmaf(qv[j].y, kr[n][j].y, s);
                s = fmaf(qv[j].z, kr[n][j].z, s);
                s = fmaf(qv[j].w, kr[n][j].w, s);
            }
            s *= TEMP_INV;
            g_logits[t * 9 + m * 3 + n] = s;
            lmin = fminf(lmin, s);
        }
    }
#pragma unroll
    for (int off = 16; off; off >>= 1)
        lmin = fminf(lmin, __shfl_xor_sync(0xFFFFFFFFu, lmin, off));
    if ((threadIdx.x & 31) == 0) atomicMin(&g_minkey, f2key(lmin));
}

// ------------- scale / L1 / softmax / PV --------------------------------------
__global__ void __launch_bounds__(256) attn_softmax_o_kernel()
{
    int t  = blockIdx.x * blockDim.x + threadIdx.x;
    int bs = t >> 3, h = t & 7;
    float inv = 1.0f / fabsf(key2f(g_minkey));

    const float* lg = g_logits + t * 9;
    const float4* vb = (const float4*)(g_v + bs * QKV_LD + h * 32);
    float* ob = g_o + bs * QKV_LD + h * 32;

#pragma unroll
    for (int m = 0; m < 3; m++) {
        float r0 = lg[m*3+0]*inv, r1 = lg[m*3+1]*inv, r2 = lg[m*3+2]*inv;
        float l1 = fmaxf(fabsf(r0) + fabsf(r1) + fabsf(r2), 1e-12f);
        r0 /= l1; r1 /= l1; r2 /= l1;
        float mx = fmaxf(r0, fmaxf(r1, r2));
        float e0 = expf(r0-mx), e1 = expf(r1-mx), e2 = expf(r2-mx);
        float es = e0 + e1 + e2;
        float p0 = e0/es, p1 = e1/es, p2 = e2/es;

        float4* o4 = (float4*)(ob + m * 256);
#pragma unroll
        for (int j = 0; j < 8; j++) {
            float4 v0 = vb[j], v1 = vb[64+j], v2 = vb[128+j];
            float4 r;
            r.x = p0*v0.x + p1*v1.x + p2*v2.x;
            r.y = p0*v0.y + p1*v1.y + p2*v2.y;
            r.z = p0*v0.z + p1*v1.z + p2*v2.z;
            r.w = p0*v0.w + p1*v1.w + p2*v2.w;
            o4[j] = r;
        }
    }
}

// ------------- residual + layernorm -------------------------------------------
__global__ void __launch_bounds__(256) ln_kernel(
    const float* __restrict__ ln_g, const float* __restrict__ ln_b)
{
    int row  = blockIdx.x * 8 + (threadIdx.x >> 5);
    int lane = threadIdx.x & 31;
    const float* fr = g_fc + (size_t)row * 256;
    const float* vr = g_v  + (size_t)row * 256;

    float x[8];
#pragma unroll
    for (int i = 0; i < 8; i++) x[i] = fr[lane + i*32] + vr[lane + i*32];

    float s = 0.f;
#pragma unroll
    for (int i = 0; i < 8; i++) s += x[i];
#pragma unroll
    for (int off = 16; off; off >>= 1) s += __shfl_xor_sync(0xFFFFFFFFu, s, off);
    float mu = s * (1.0f/256.0f);

    float ss = 0.f;
#pragma unroll
    for (int i = 0; i < 8; i++) { float d = x[i]-mu; ss += d*d; }
#pragma unroll
    for (int off = 16; off; off >>= 1) ss += __shfl_xor_sync(0xFFFFFFFFu, ss, off);
    float rstd = rsqrtf(ss * (1.0f/256.0f) + LN_EPS);

    float* xr = g_x + (size_t)row * 256;
#pragma unroll
    for (int i = 0; i < 8; i++) {
        int idx = lane + i*32;
        xr[idx] = (x[i]-mu)*rstd*ln_g[idx] + ln_b[idx];
    }
}

// ------------- final skinny GEMM [BS,768] @ [768,5] ---------------------------
__global__ void __launch_bounds__(256) out_kernel(
    const float* __restrict__ out_w, const float* __restrict__ out_b,
    float* __restrict__ out)
{
    __shared__ float sw[768 * 5];
    for (int i = threadIdx.x; i < 768*5; i += 256) sw[i] = out_w[i];
    __syncthreads();

    int samp = blockIdx.x * 8 + (threadIdx.x >> 5);
    int lane = threadIdx.x & 31;
    const float* xr = g_x + (size_t)samp * 768;

    float acc[5] = {0.f, 0.f, 0.f, 0.f, 0.f};
    for (int i = lane; i < 768; i += 32) {
        float xv = xr[i];
#pragma unroll
        for (int c = 0; c < 5; c++) acc[c] = fmaf(xv, sw[i*5+c], acc[c]);
    }
#pragma unroll
    for (int off = 16; off; off >>= 1)
#pragma unroll
        for (int c = 0; c < 5; c++)
            acc[c] += __shfl_xor_sync(0xFFFFFFFFu, acc[c], off);

    if (lane < 5) out[samp*5 + lane] = acc[lane] + out_b[lane];
}

// ==============================================================================
extern "C" void kernel_launch(void* const* d_in, const int* in_sizes, int n_in,
                              void* d_out, int out_size)
{
    const float* X = (const float*)d_in[0];
    W9 ws; B9 bs;
    for (int t = 0; t < 3; t++)
        for (int m = 0; m < 3; m++) {
            ws.w[t*3+m] = (const float*)d_in[1 + t*6 + m*2];
            bs.b[t*3+m] = (const float*)d_in[2 + t*6 + m*2];
        }
    const float* fc_w  = (const float*)d_in[19];
    const float* fc_b  = (const float*)d_in[20];
    const float* ln_g  = (const float*)d_in[21];
    const float* ln_b  = (const float*)d_in[22];
    const float* out_w = (const float*)d_in[23];
    const float* out_b = (const float*)d_in[24];
    float* out = (float*)d_out;

    static int smem_set = 0;
    if (!smem_set) {
        cudaFuncSetAttribute(qkv_gemm_kernel, cudaFuncAttributeMaxDynamicSharedMemorySize, SMEM_GEMM);
        cudaFuncSetAttribute(fc_gemm_kernel,  cudaFuncAttributeMaxDynamicSharedMemorySize, SMEM_GEMM);
        smem_set = 1;
    }

    init_min_kernel<<<1, 1>>>();
    conv_x_kernel<<<dim3(6, BSZ), 256>>>(X);
    conv_w_kernel<<<dim3(1024, 1, 9), 256>>>(ws);
    conv_fcw_kernel<<<128, 256>>>(fc_w);

    qkv_gemm_kernel<<<dim3(2, BSZ/128, 9), 256, SMEM_GEMM>>>(bs);

    attn_logits_kernel<<<(BSZ*8)/256, 256>>>();
    attn_softmax_o_kernel<<<(BSZ*8)/256, 256>>>();

    conv_o_kernel<<<(NROWS*256/2)/256, 256>>>();
    fc_gemm_kernel<<<dim3(2, NROWS/128, 1), 256, SMEM_GEMM>>>(fc_b);

    ln_kernel<<<NROWS/8, 256>>>(ln_g, ln_b);
    out_kernel<<<BSZ/8, 256>>>(out_w, out_b, out);
}

// round 4
// speedup vs baseline: 2.1729x; 1.0929x over previous
#include <cuda_runtime.h>
#include <cuda_bf16.h>
#include <cstdint>

#define BSZ    16384
#define QKV_LD 768
#define NROWS  (BSZ*3)
#define LN_EPS 1e-6f
#define TEMP_INV 0.17677669529663687f
#define APAD   3072      // padded concat K: 2048 + 512 + 512

// ---------------- scratch (static device arrays; no cudaMalloc) --------------
__device__ __align__(16) float g_q [BSZ*QKV_LD];
__device__ __align__(16) float g_k [BSZ*QKV_LD];
__device__ __align__(16) float g_v [BSZ*QKV_LD];
__device__ __align__(16) float g_o [BSZ*QKV_LD];
__device__ __align__(16) float g_fc[BSZ*QKV_LD];
__device__ __align__(16) float g_x [BSZ*QKV_LD];
__device__ __align__(16) float g_logits[BSZ*8*9];
__device__ unsigned g_minkey;

__device__ __align__(16) __nv_bfloat16 g_ah[(size_t)BSZ*APAD];
__device__ __align__(16) __nv_bfloat16 g_al[(size_t)BSZ*APAD];
__device__ __align__(16) __nv_bfloat16 g_wh[(size_t)3*256*APAD];
__device__ __align__(16) __nv_bfloat16 g_wl[(size_t)3*256*APAD];
__device__ __align__(16) __nv_bfloat16 g_oh[(size_t)NROWS*256];
__device__ __align__(16) __nv_bfloat16 g_ol[(size_t)NROWS*256];
__device__ __align__(16) __nv_bfloat16 g_fch[256*256];
__device__ __align__(16) __nv_bfloat16 g_fcl[256*256];

// ---------------- small helpers ----------------------------------------------
__device__ __forceinline__ unsigned f2key(float f) {
    unsigned u = __float_as_uint(f);
    return (u & 0x80000000u) ? ~u : (u | 0x80000000u);
}
__device__ __forceinline__ float key2f(unsigned k) {
    unsigned u = (k & 0x80000000u) ? (k & 0x7FFFFFFFu) : ~k;
    return __uint_as_float(u);
}
__global__ void init_min_kernel() { g_minkey = 0xFFFFFFFFu; }

__device__ __forceinline__ uint32_t su32(const void* p) {
    return (uint32_t)__cvta_generic_to_shared(p);
}
__device__ __forceinline__ void cp16(uint32_t dst, const void* src) {
    asm volatile("cp.async.cg.shared.global [%0], [%1], 16;"
                 :: "r"(dst), "l"(src) : "memory");
}
__device__ __forceinline__ void cp_commit() {
    asm volatile("cp.async.commit_group;" ::: "memory");
}
__device__ __forceinline__ void ldm_x4(uint32_t& r0, uint32_t& r1, uint32_t& r2,
                                       uint32_t& r3, uint32_t addr) {
    asm volatile("ldmatrix.sync.aligned.m8n8.x4.shared.b16 {%0,%1,%2,%3}, [%4];"
                 : "=r"(r0), "=r"(r1), "=r"(r2), "=r"(r3) : "r"(addr));
}
__device__ __forceinline__ void mma_bf16(float* c, uint32_t a0, uint32_t a1,
                                         uint32_t a2, uint32_t a3,
                                         uint32_t b0, uint32_t b1) {
    asm volatile(
        "mma.sync.aligned.m16n8k16.row.col.f32.bf16.bf16.f32 "
        "{%0,%1,%2,%3}, {%4,%5,%6,%7}, {%8,%9}, {%0,%1,%2,%3};"
        : "+f"(c[0]), "+f"(c[1]), "+f"(c[2]), "+f"(c[3])
        : "r"(a0), "r"(a1), "r"(a2), "r"(a3), "r"(b0), "r"(b1));
}
__device__ __forceinline__ void split_bf16(float v, __nv_bfloat16& h, __nv_bfloat16& l) {
    h = __float2bfloat16(v);
    l = __float2bfloat16(v - __bfloat162float(h));
}

// ---------------- conversion kernels -----------------------------------------
__global__ void __launch_bounds__(256) conv_x_kernel(const float* __restrict__ X)
{
    int col2 = (blockIdx.x * 256 + threadIdx.x) * 2;
    int row  = blockIdx.y;
    __nv_bfloat16 h[2], l[2];
#pragma unroll
    for (int e = 0; e < 2; e++) {
        int col = col2 + e;
        float x = 0.f;
        if (col < 2048)      { if (col < 2000) x = X[(size_t)row*2900 + col]; }
        else if (col < 2560) { int c = col-2048; if (c < 500) x = X[(size_t)row*2900 + 2000 + c]; }
        else                 { int c = col-2560; if (c < 400) x = X[(size_t)row*2900 + 2500 + c]; }
        split_bf16(x, h[e], l[e]);
    }
    __nv_bfloat162 hh; hh.x = h[0]; hh.y = h[1];
    __nv_bfloat162 ll; ll.x = l[0]; ll.y = l[1];
    *(__nv_bfloat162*)&g_ah[(size_t)row*APAD + col2] = hh;
    *(__nv_bfloat162*)&g_al[(size_t)row*APAD + col2] = ll;
}

struct W9 { const float* w[9]; };
__global__ void __launch_bounds__(256) conv_w_kernel(W9 ws)
{
    const int Km[3]   = {2000, 500, 400};
    const int Kp[3]   = {2048, 512, 512};
    const int colA[3] = {0, 2048, 2560};
    int z = blockIdx.z, t = z / 3, m = z - t * 3;
    int idx = (blockIdx.x * 256 + threadIdx.x) * 2;
    if (idx >= 256 * Kp[m]) return;
    int n  = idx / Kp[m];
    int kp = idx - n * Kp[m];
    const float* W = ws.w[z];
    float x0 = (kp     < Km[m]) ? W[(size_t)kp*256 + n]     : 0.f;
    float x1 = (kp + 1 < Km[m]) ? W[(size_t)(kp+1)*256 + n] : 0.f;
    __nv_bfloat16 h0, l0, h1, l1;
    split_bf16(x0, h0, l0); split_bf16(x1, h1, l1);
    size_t o = (size_t)t*256*APAD + (size_t)n*APAD + colA[m] + kp;
    __nv_bfloat162 hh; hh.x = h0; hh.y = h1;
    __nv_bfloat162 ll; ll.x = l0; ll.y = l1;
    *(__nv_bfloat162*)&g_wh[o] = hh;
    *(__nv_bfloat162*)&g_wl[o] = ll;
}

__global__ void __launch_bounds__(256) conv_fcw_kernel(const float* __restrict__ fcw)
{
    int idx = (blockIdx.x * 256 + threadIdx.x) * 2;
    int n = idx >> 8, k = idx & 255;
    float x0 = fcw[(size_t)k*256 + n];
    float x1 = fcw[(size_t)(k+1)*256 + n];
    __nv_bfloat16 h0, l0, h1, l1;
    split_bf16(x0, h0, l0); split_bf16(x1, h1, l1);
    __nv_bfloat162 hh; hh.x = h0; hh.y = h1;
    __nv_bfloat162 ll; ll.x = l0; ll.y = l1;
    *(__nv_bfloat162*)&g_fch[n*256 + k] = hh;
    *(__nv_bfloat162*)&g_fcl[n*256 + k] = ll;
}

__global__ void __launch_bounds__(256) conv_o_kernel()
{
    size_t i2 = ((size_t)blockIdx.x * 256 + threadIdx.x) * 2;
    float2 v = *(const float2*)&g_o[i2];
    __nv_bfloat16 h0, l0, h1, l1;
    split_bf16(v.x, h0, l0); split_bf16(v.y, h1, l1);
    __nv_bfloat162 hh; hh.x = h0; hh.y = h1;
    __nv_bfloat162 ll; ll.x = l0; ll.y = l1;
    *(__nv_bfloat162*)&g_oh[i2] = hh;
    *(__nv_bfloat162*)&g_ol[i2] = ll;
}

// ---------------- mma.sync split-bf16 GEMM -------------------------------------
// C[M,256] = (Ah+Al)[M,K] @ B(hi/lo)[256,K]-rows + bias
// pass 1: for each Ah chunk, accumulate Ah@Bh + Ah@Bl (A loaded once)
// pass 2: Al@Bh
struct GP {
    const __nv_bfloat16 *Ah, *Al, *Bh, *Bl;
    int ldA, ldB, colA, colB, Kp;
    const float* bias;
    float* C; int ldc;
};

// stage: A 128x144B + Bh 128x144B + Bl 128x144B  (K-chunk 64, 144B padded rows)
#define SOFF_BH 18432
#define SOFF_BL 36864
#define SSTG    55296
#define SMEM_GEMM (3*SSTG)

__device__ __forceinline__ void gemm_body(const GP p)
{
    extern __shared__ __align__(16) char dsm[];
    const int tid  = threadIdx.x;
    const int lane = tid & 31, wid = tid >> 5;
    const int wm = wid >> 2, wn = wid & 3;            // 2x4 warp grid
    const int row0 = blockIdx.y * 128, col0 = blockIdx.x * 128;
    const uint32_t sbase = su32(dsm);

    const int ck = p.Kp >> 6;          // K=64 chunks per segment
    const int nchunk = 2 * ck;         // pass1 (Ah) + pass2 (Al)

    auto load_chunk = [&](int c) {
        int seg = (c >= ck);
        int kc  = seg ? c - ck : c;
        const __nv_bfloat16* A  = seg ? p.Al : p.Ah;
        const __nv_bfloat16* As = A + (size_t)row0 * p.ldA + p.colA + kc * 64;
        const __nv_bfloat16* Bh = p.Bh + (size_t)col0 * p.ldB + p.colB + kc * 64;
        const __nv_bfloat16* Bl = p.Bl + (size_t)col0 * p.ldB + p.colB + kc * 64;
        uint32_t Sd = sbase + (c % 3) * SSTG;
#pragma unroll
        for (int i = 0; i < 4; i++) {
            int id = i * 256 + tid, r = id >> 3, kg = id & 7;
            cp16(Sd + r * 144 + kg * 16, As + (size_t)r * p.ldA + kg * 8);
            cp16(Sd + SOFF_BH + r * 144 + kg * 16, Bh + (size_t)r * p.ldB + kg * 8);
            if (!seg)
                cp16(Sd + SOFF_BL + r * 144 + kg * 16, Bl + (size_t)r * p.ldB + kg * 8);
        }
    };

    float acc[4][4][4];
#pragma unroll
    for (int i = 0; i < 4; i++)
#pragma unroll
        for (int j = 0; j < 4; j++)
#pragma unroll
            for (int r = 0; r < 4; r++) acc[i][j][r] = 0.f;

    load_chunk(0); cp_commit();

    // per-lane ldmatrix byte offsets (144B smem row stride)
    const uint32_t a_off = (uint32_t)((wm * 64 + (lane & 15)) * 144 + ((lane >> 4) << 4));
    const uint32_t b_off = (uint32_t)((wn * 32 + (lane & 7) + ((lane & 16) >> 1)) * 144
                                      + ((lane & 8) << 1));

    for (int c = 0; c < nchunk; c++) {
        if (c + 1 < nchunk) {
            load_chunk(c + 1); cp_commit();
            asm volatile("cp.async.wait_group 1;" ::: "memory");
        } else {
            asm volatile("cp.async.wait_group 0;" ::: "memory");
        }
        __syncthreads();

        const uint32_t Sd = sbase + (c % 3) * SSTG;
        const uint32_t Ab = Sd + a_off;
        const uint32_t Bb = Sd + SOFF_BH + b_off;
        const int pass1 = (c < ck);
#pragma unroll
        for (int kstep = 0; kstep < 4; kstep++) {
            const uint32_t kk = kstep * 32;
            uint32_t a[4][4], bh[2][4];
#pragma unroll
            for (int mt = 0; mt < 4; mt++)
                ldm_x4(a[mt][0], a[mt][1], a[mt][2], a[mt][3],
                       Ab + mt * (16 * 144) + kk);
#pragma unroll
            for (int ng = 0; ng < 2; ng++)
                ldm_x4(bh[ng][0], bh[ng][1], bh[ng][2], bh[ng][3],
                       Bb + ng * (16 * 144) + kk);
#pragma unroll
            for (int mt = 0; mt < 4; mt++)
#pragma unroll
                for (int nt = 0; nt < 4; nt++)
                    mma_bf16(acc[mt][nt],
                             a[mt][0], a[mt][1], a[mt][2], a[mt][3],
                             bh[nt >> 1][(nt & 1) * 2], bh[nt >> 1][(nt & 1) * 2 + 1]);
            if (pass1) {
                uint32_t bl[2][4];
#pragma unroll
                for (int ng = 0; ng < 2; ng++)
                    ldm_x4(bl[ng][0], bl[ng][1], bl[ng][2], bl[ng][3],
                           Bb + (SOFF_BL - SOFF_BH) + ng * (16 * 144) + kk);
#pragma unroll
                for (int mt = 0; mt < 4; mt++)
#pragma unroll
                    for (int nt = 0; nt < 4; nt++)
                        mma_bf16(acc[mt][nt],
                                 a[mt][0], a[mt][1], a[mt][2], a[mt][3],
                                 bl[nt >> 1][(nt & 1) * 2], bl[nt >> 1][(nt & 1) * 2 + 1]);
            }
        }
    }

    // epilogue
    const int grp = lane >> 2, tig = lane & 3;
#pragma unroll
    for (int mt = 0; mt < 4; mt++) {
        int r = row0 + wm * 64 + mt * 16 + grp;
#pragma unroll
        for (int nt = 0; nt < 4; nt++) {
            int col = col0 + wn * 32 + nt * 8 + tig * 2;
            float b0 = p.bias[col], b1 = p.bias[col + 1];
            float2 lo, hi;
            lo.x = acc[mt][nt][0] + b0; lo.y = acc[mt][nt][1] + b1;
            hi.x = acc[mt][nt][2] + b0; hi.y = acc[mt][nt][3] + b1;
            *(float2*)(p.C + (size_t)r * p.ldc + col) = lo;
            *(float2*)(p.C + (size_t)(r + 8) * p.ldc + col) = hi;
        }
    }
}

struct B9 { const float* b[9]; };

// z = m*3 + t  (modality outer -> q/k/v of same modality adjacent: A stays L2-hot)
__global__ void __launch_bounds__(256) qkv_gemm_kernel(B9 biases)
{
    const int colA[3] = {0, 2048, 2560};
    const int Kp[3]   = {2048, 512, 512};
    int z = blockIdx.z, m = z / 3, t = z - m * 3;
    GP p;
    p.Ah = g_ah; p.Al = g_al; p.ldA = APAD; p.colA = colA[m];
    p.Bh = g_wh + (size_t)t * 256 * APAD;
    p.Bl = g_wl + (size_t)t * 256 * APAD;
    p.ldB = APAD; p.colB = colA[m];
    p.Kp = Kp[m];
    p.bias = biases.b[t * 3 + m];
    p.C = ((t == 0) ? g_q : (t == 1) ? g_k : g_v) + m * 256;
    p.ldc = QKV_LD;
    gemm_body(p);
}

__global__ void __launch_bounds__(256) fc_gemm_kernel(const float* fc_b)
{
    GP p;
    p.Ah = g_oh; p.Al = g_ol; p.ldA = 256; p.colA = 0;
    p.Bh = g_fch; p.Bl = g_fcl; p.ldB = 256; p.colB = 0;
    p.Kp = 256;
    p.bias = fc_b; p.C = g_fc; p.ldc = 256;
    gemm_body(p);
}

// ------------- attention logits + global min ---------------------------------
__global__ void __launch_bounds__(256) attn_logits_kernel()
{
    int t  = blockIdx.x * blockDim.x + threadIdx.x;
    int bs = t >> 3, h = t & 7;
    const float4* qb = (const float4*)(g_q + bs * QKV_LD + h * 32);
    const float4* kb = (const float4*)(g_k + bs * QKV_LD + h * 32);

    float4 kr[3][8];
#pragma unroll
    for (int n = 0; n < 3; n++)
#pragma unroll
        for (int j = 0; j < 8; j++) kr[n][j] = kb[n * 64 + j];

    float lmin = 3.4e38f;
#pragma unroll
    for (int m = 0; m < 3; m++) {
        float4 qv[8];
#pragma unroll
        for (int j = 0; j < 8; j++) qv[j] = qb[m * 64 + j];
#pragma unroll
        for (int n = 0; n < 3; n++) {
            float s = 0.f;
#pragma unroll
            for (int j = 0; j < 8; j++) {
                s = fmaf(qv[j].x, kr[n][j].x, s);
                s = fmaf(qv[j].y, kr[n][j].y, s);
                s = fmaf(qv[j].z, kr[n][j].z, s);
                s = fmaf(qv[j].w, kr[n][j].w, s);
            }
            s *= TEMP_INV;
            g_logits[t * 9 + m * 3 + n] = s;
            lmin = fminf(lmin, s);
        }
    }
#pragma unroll
    for (int off = 16; off; off >>= 1)
        lmin = fminf(lmin, __shfl_xor_sync(0xFFFFFFFFu, lmin, off));
    if ((threadIdx.x & 31) == 0) atomicMin(&g_minkey, f2key(lmin));
}

// ------------- scale / L1 / softmax / PV --------------------------------------
__global__ void __launch_bounds__(256) attn_softmax_o_kernel()
{
    int t  = blockIdx.x * blockDim.x + threadIdx.x;
    int bs = t >> 3, h = t & 7;
    float inv = 1.0f / fabsf(key2f(g_minkey));

    const float* lg = g_logits + t * 9;
    const float4* vb = (const float4*)(g_v + bs * QKV_LD + h * 32);
    float* ob = g_o + bs * QKV_LD + h * 32;

#pragma unroll
    for (int m = 0; m < 3; m++) {
        float r0 = lg[m*3+0]*inv, r1 = lg[m*3+1]*inv, r2 = lg[m*3+2]*inv;
        float l1 = fmaxf(fabsf(r0) + fabsf(r1) + fabsf(r2), 1e-12f);
        r0 /= l1; r1 /= l1; r2 /= l1;
        float mx = fmaxf(r0, fmaxf(r1, r2));
        float e0 = expf(r0-mx), e1 = expf(r1-mx), e2 = expf(r2-mx);
        float es = e0 + e1 + e2;
        float p0 = e0/es, p1 = e1/es, p2 = e2/es;

        float4* o4 = (float4*)(ob + m * 256);
#pragma unroll
        for (int j = 0; j < 8; j++) {
            float4 v0 = vb[j], v1 = vb[64+j], v2 = vb[128+j];
            float4 r;
            r.x = p0*v0.x + p1*v1.x + p2*v2.x;
            r.y = p0*v0.y + p1*v1.y + p2*v2.y;
            r.z = p0*v0.z + p1*v1.z + p2*v2.z;
            r.w = p0*v0.w + p1*v1.w + p2*v2.w;
            o4[j] = r;
        }
    }
}

// ------------- residual + layernorm -------------------------------------------
__global__ void __launch_bounds__(256) ln_kernel(
    const float* __restrict__ ln_g, const float* __restrict__ ln_b)
{
    int row  = blockIdx.x * 8 + (threadIdx.x >> 5);
    int lane = threadIdx.x & 31;
    const float* fr = g_fc + (size_t)row * 256;
    const float* vr = g_v  + (size_t)row * 256;

    float x[8];
#pragma unroll
    for (int i = 0; i < 8; i++) x[i] = fr[lane + i*32] + vr[lane + i*32];

    float s = 0.f;
#pragma unroll
    for (int i = 0; i < 8; i++) s += x[i];
#pragma unroll
    for (int off = 16; off; off >>= 1) s += __shfl_xor_sync(0xFFFFFFFFu, s, off);
    float mu = s * (1.0f/256.0f);

    float ss = 0.f;
#pragma unroll
    for (int i = 0; i < 8; i++) { float d = x[i]-mu; ss += d*d; }
#pragma unroll
    for (int off = 16; off; off >>= 1) ss += __shfl_xor_sync(0xFFFFFFFFu, ss, off);
    float rstd = rsqrtf(ss * (1.0f/256.0f) + LN_EPS);

    float* xr = g_x + (size_t)row * 256;
#pragma unroll
    for (int i = 0; i < 8; i++) {
        int idx = lane + i*32;
        xr[idx] = (x[i]-mu)*rstd*ln_g[idx] + ln_b[idx];
    }
}

// ------------- final skinny GEMM [BS,768] @ [768,5] ---------------------------
__global__ void __launch_bounds__(256) out_kernel(
    const float* __restrict__ out_w, const float* __restrict__ out_b,
    float* __restrict__ out)
{
    __shared__ float sw[768 * 5];
    for (int i = threadIdx.x; i < 768*5; i += 256) sw[i] = out_w[i];
    __syncthreads();

    int samp = blockIdx.x * 8 + (threadIdx.x >> 5);
    int lane = threadIdx.x & 31;
    const float* xr = g_x + (size_t)samp * 768;

    float acc[5] = {0.f, 0.f, 0.f, 0.f, 0.f};
    for (int i = lane; i < 768; i += 32) {
        float xv = xr[i];
#pragma unroll
        for (int c = 0; c < 5; c++) acc[c] = fmaf(xv, sw[i*5+c], acc[c]);
    }
#pragma unroll
    for (int off = 16; off; off >>= 1)
#pragma unroll
        for (int c = 0; c < 5; c++)
            acc[c] += __shfl_xor_sync(0xFFFFFFFFu, acc[c], off);

    if (lane < 5) out[samp*5 + lane] = acc[lane] + out_b[lane];
}

// ==============================================================================
extern "C" void kernel_launch(void* const* d_in, const int* in_sizes, int n_in,
                              void* d_out, int out_size)
{
    const float* X = (const float*)d_in[0];
    W9 ws; B9 bs;
    for (int t = 0; t < 3; t++)
        for (int m = 0; m < 3; m++) {
            ws.w[t*3+m] = (const float*)d_in[1 + t*6 + m*2];
            bs.b[t*3+m] = (const float*)d_in[2 + t*6 + m*2];
        }
    const float* fc_w  = (const float*)d_in[19];
    const float* fc_b  = (const float*)d_in[20];
    const float* ln_g  = (const float*)d_in[21];
    const float* ln_b  = (const float*)d_in[22];
    const float* out_w = (const float*)d_in[23];
    const float* out_b = (const float*)d_in[24];
    float* out = (float*)d_out;

    static int smem_set = 0;
    if (!smem_set) {
        cudaFuncSetAttribute(qkv_gemm_kernel, cudaFuncAttributeMaxDynamicSharedMemorySize, SMEM_GEMM);
        cudaFuncSetAttribute(fc_gemm_kernel,  cudaFuncAttributeMaxDynamicSharedMemorySize, SMEM_GEMM);
        smem_set = 1;
    }

    init_min_kernel<<<1, 1>>>();
    conv_x_kernel<<<dim3(6, BSZ), 256>>>(X);
    conv_w_kernel<<<dim3(1024, 1, 9), 256>>>(ws);
    conv_fcw_kernel<<<128, 256>>>(fc_w);

    qkv_gemm_kernel<<<dim3(2, BSZ/128, 9), 256, SMEM_GEMM>>>(bs);

    attn_logits_kernel<<<(BSZ*8)/256, 256>>>();
    attn_softmax_o_kernel<<<(BSZ*8)/256, 256>>>();

    conv_o_kernel<<<(NROWS*256/2)/256, 256>>>();
    fc_gemm_kernel<<<dim3(2, NROWS/128, 1), 256, SMEM_GEMM>>>(fc_b);

    ln_kernel<<<NROWS/8, 256>>>(ln_g, ln_b);
    out_kernel<<<BSZ/8, 256>>>(out_w, out_b, out);
}

// round 5
// speedup vs baseline: 2.4362x; 1.1211x over previous
#include <cuda_runtime.h>
#include <cuda_bf16.h>
#include <cstdint>

#define BSZ    16384
#define QKV_LD 768
#define NROWS  (BSZ*3)
#define LN_EPS 1e-6f
#define TEMP_INV 0.17677669529663687f
#define APAD   3072      // padded concat K: 2048 + 512 + 512

// ---------------- scratch (static device arrays; no cudaMalloc) --------------
__device__ __align__(16) float g_q [BSZ*QKV_LD];
__device__ __align__(16) float g_k [BSZ*QKV_LD];
__device__ __align__(16) float g_v [BSZ*QKV_LD];
__device__ __align__(16) float g_o [BSZ*QKV_LD];
__device__ __align__(16) float g_fc[BSZ*QKV_LD];
__device__ __align__(16) float g_x [BSZ*QKV_LD];
__device__ __align__(16) float g_logits[BSZ*8*9];
__device__ unsigned g_minkey;

__device__ __align__(16) __nv_bfloat16 g_ah[(size_t)BSZ*APAD];
__device__ __align__(16) __nv_bfloat16 g_al[(size_t)BSZ*APAD];
__device__ __align__(16) __nv_bfloat16 g_wh[(size_t)3*256*APAD];
__device__ __align__(16) __nv_bfloat16 g_wl[(size_t)3*256*APAD];
__device__ __align__(16) __nv_bfloat16 g_oh[(size_t)NROWS*256];
__device__ __align__(16) __nv_bfloat16 g_ol[(size_t)NROWS*256];
__device__ __align__(16) __nv_bfloat16 g_fch[256*256];
__device__ __align__(16) __nv_bfloat16 g_fcl[256*256];

// ---------------- small helpers ----------------------------------------------
__device__ __forceinline__ unsigned f2key(float f) {
    unsigned u = __float_as_uint(f);
    return (u & 0x80000000u) ? ~u : (u | 0x80000000u);
}
__device__ __forceinline__ float key2f(unsigned k) {
    unsigned u = (k & 0x80000000u) ? (k & 0x7FFFFFFFu) : ~k;
    return __uint_as_float(u);
}
__global__ void init_min_kernel() { g_minkey = 0xFFFFFFFFu; }
__global__ void noop_kernel() {}     // spacer so ncu -s 5 profiles qkv_gemm

__device__ __forceinline__ uint32_t su32(const void* p) {
    return (uint32_t)__cvta_generic_to_shared(p);
}
__device__ __forceinline__ void cp16(uint32_t dst, const void* src) {
    asm volatile("cp.async.cg.shared.global [%0], [%1], 16;"
                 :: "r"(dst), "l"(src) : "memory");
}
__device__ __forceinline__ void cp_commit() {
    asm volatile("cp.async.commit_group;" ::: "memory");
}
__device__ __forceinline__ void ldm_x4(uint32_t& r0, uint32_t& r1, uint32_t& r2,
                                       uint32_t& r3, uint32_t addr) {
    asm volatile("ldmatrix.sync.aligned.m8n8.x4.shared.b16 {%0,%1,%2,%3}, [%4];"
                 : "=r"(r0), "=r"(r1), "=r"(r2), "=r"(r3) : "r"(addr));
}
__device__ __forceinline__ void mma_bf16(float* c, uint32_t a0, uint32_t a1,
                                         uint32_t a2, uint32_t a3,
                                         uint32_t b0, uint32_t b1) {
    asm volatile(
        "mma.sync.aligned.m16n8k16.row.col.f32.bf16.bf16.f32 "
        "{%0,%1,%2,%3}, {%4,%5,%6,%7}, {%8,%9}, {%0,%1,%2,%3};"
        : "+f"(c[0]), "+f"(c[1]), "+f"(c[2]), "+f"(c[3])
        : "r"(a0), "r"(a1), "r"(a2), "r"(a3), "r"(b0), "r"(b1));
}
__device__ __forceinline__ void split_bf16(float v, __nv_bfloat16& h, __nv_bfloat16& l) {
    h = __float2bfloat16(v);
    l = __float2bfloat16(v - __bfloat162float(h));
}

// ---------------- conversion kernels -----------------------------------------
__global__ void __launch_bounds__(256) conv_x_kernel(const float* __restrict__ X)
{
    int col2 = (blockIdx.x * 256 + threadIdx.x) * 2;
    int row  = blockIdx.y;
    __nv_bfloat16 h[2], l[2];
#pragma unroll
    for (int e = 0; e < 2; e++) {
        int col = col2 + e;
        float x = 0.f;
        if (col < 2048)      { if (col < 2000) x = X[(size_t)row*2900 + col]; }
        else if (col < 2560) { int c = col-2048; if (c < 500) x = X[(size_t)row*2900 + 2000 + c]; }
        else                 { int c = col-2560; if (c < 400) x = X[(size_t)row*2900 + 2500 + c]; }
        split_bf16(x, h[e], l[e]);
    }
    __nv_bfloat162 hh; hh.x = h[0]; hh.y = h[1];
    __nv_bfloat162 ll; ll.x = l[0]; ll.y = l[1];
    *(__nv_bfloat162*)&g_ah[(size_t)row*APAD + col2] = hh;
    *(__nv_bfloat162*)&g_al[(size_t)row*APAD + col2] = ll;
}

struct W9 { const float* w[9]; };
__global__ void __launch_bounds__(256) conv_w_kernel(W9 ws)
{
    const int Km[3]   = {2000, 500, 400};
    const int Kp[3]   = {2048, 512, 512};
    const int colA[3] = {0, 2048, 2560};
    int z = blockIdx.z, t = z / 3, m = z - t * 3;
    int idx = (blockIdx.x * 256 + threadIdx.x) * 2;
    if (idx >= 256 * Kp[m]) return;
    int n  = idx / Kp[m];
    int kp = idx - n * Kp[m];
    const float* W = ws.w[z];
    float x0 = (kp     < Km[m]) ? W[(size_t)kp*256 + n]     : 0.f;
    float x1 = (kp + 1 < Km[m]) ? W[(size_t)(kp+1)*256 + n] : 0.f;
    __nv_bfloat16 h0, l0, h1, l1;
    split_bf16(x0, h0, l0); split_bf16(x1, h1, l1);
    size_t o = (size_t)t*256*APAD + (size_t)n*APAD + colA[m] + kp;
    __nv_bfloat162 hh; hh.x = h0; hh.y = h1;
    __nv_bfloat162 ll; ll.x = l0; ll.y = l1;
    *(__nv_bfloat162*)&g_wh[o] = hh;
    *(__nv_bfloat162*)&g_wl[o] = ll;
}

__global__ void __launch_bounds__(256) conv_fcw_kernel(const float* __restrict__ fcw)
{
    int idx = (blockIdx.x * 256 + threadIdx.x) * 2;
    int n = idx >> 8, k = idx & 255;
    float x0 = fcw[(size_t)k*256 + n];
    float x1 = fcw[(size_t)(k+1)*256 + n];
    __nv_bfloat16 h0, l0, h1, l1;
    split_bf16(x0, h0, l0); split_bf16(x1, h1, l1);
    __nv_bfloat162 hh; hh.x = h0; hh.y = h1;
    __nv_bfloat162 ll; ll.x = l0; ll.y = l1;
    *(__nv_bfloat162*)&g_fch[n*256 + k] = hh;
    *(__nv_bfloat162*)&g_fcl[n*256 + k] = ll;
}

__global__ void __launch_bounds__(256) conv_o_kernel()
{
    size_t i2 = ((size_t)blockIdx.x * 256 + threadIdx.x) * 2;
    float2 v = *(const float2*)&g_o[i2];
    __nv_bfloat16 h0, l0, h1, l1;
    split_bf16(v.x, h0, l0); split_bf16(v.y, h1, l1);
    __nv_bfloat162 hh; hh.x = h0; hh.y = h1;
    __nv_bfloat162 ll; ll.x = l0; ll.y = l1;
    *(__nv_bfloat162*)&g_oh[i2] = hh;
    *(__nv_bfloat162*)&g_ol[i2] = ll;
}

// ---------------- mma.sync split-bf16 GEMM -------------------------------------
// C[M,256] = (Ah+Al)[M,K] @ B(hi/lo)[256,K]-rows + bias
// pass 1: Ah chunks, accumulate Ah@Bh + Ah@Bl; pass 2: Al@Bh
struct GP {
    const __nv_bfloat16 *Ah, *Al, *Bh, *Bl;
    int ldA, ldB, colA, colB, Kp;
    const float* bias;
    float* C; int ldc;
};

// stage: A 128x80B + Bh 128x80B + Bl 128x80B  (K-chunk 32, 80B padded rows)
#define SOFF_BH 10240
#define SOFF_BL 20480
#define SSTG    30720
#define SMEM_GEMM (3*SSTG)   // 92160 -> 2 CTAs/SM

__device__ __forceinline__ void gemm_body(const GP p)
{
    extern __shared__ __align__(16) char dsm[];
    const int tid  = threadIdx.x;
    const int lane = tid & 31, wid = tid >> 5;
    const int wm = wid >> 2, wn = wid & 3;            // 2x4 warp grid
    const int row0 = blockIdx.y * 128, col0 = blockIdx.x * 128;
    const uint32_t sbase = su32(dsm);

    const int ck = p.Kp >> 5;          // K=32 chunks per segment
    const int nchunk = 2 * ck;         // pass1 (Ah) + pass2 (Al)

    auto load_chunk = [&](int c) {
        int seg = (c >= ck);
        int kc  = seg ? c - ck : c;
        const __nv_bfloat16* A  = seg ? p.Al : p.Ah;
        const __nv_bfloat16* As = A + (size_t)row0 * p.ldA + p.colA + kc * 32;
        const __nv_bfloat16* Bh = p.Bh + (size_t)col0 * p.ldB + p.colB + kc * 32;
        const __nv_bfloat16* Bl = p.Bl + (size_t)col0 * p.ldB + p.colB + kc * 32;
        uint32_t Sd = sbase + (c % 3) * SSTG;
#pragma unroll
        for (int i = 0; i < 2; i++) {
            int id = i * 256 + tid, r = id >> 2, kg = id & 3;
            cp16(Sd + r * 80 + kg * 16, As + (size_t)r * p.ldA + kg * 8);
            cp16(Sd + SOFF_BH + r * 80 + kg * 16, Bh + (size_t)r * p.ldB + kg * 8);
            if (!seg)
                cp16(Sd + SOFF_BL + r * 80 + kg * 16, Bl + (size_t)r * p.ldB + kg * 8);
        }
    };

    float acc[4][4][4];
#pragma unroll
    for (int i = 0; i < 4; i++)
#pragma unroll
        for (int j = 0; j < 4; j++)
#pragma unroll
            for (int r = 0; r < 4; r++) acc[i][j][r] = 0.f;

    load_chunk(0); cp_commit();

    // per-lane ldmatrix byte offsets (80B smem row stride)
    const uint32_t a_off = (uint32_t)((wm * 64 + (lane & 15)) * 80 + ((lane >> 4) << 4));
    const uint32_t b_off = (uint32_t)((wn * 32 + (lane & 7) + ((lane & 16) >> 1)) * 80
                                      + ((lane & 8) << 1));

    for (int c = 0; c < nchunk; c++) {
        if (c + 1 < nchunk) {
            load_chunk(c + 1); cp_commit();
            asm volatile("cp.async.wait_group 1;" ::: "memory");
        } else {
            asm volatile("cp.async.wait_group 0;" ::: "memory");
        }
        __syncthreads();

        const uint32_t Sd = sbase + (c % 3) * SSTG;
        const uint32_t Ab = Sd + a_off;
        const uint32_t Bb = Sd + SOFF_BH + b_off;
        const int pass1 = (c < ck);
#pragma unroll
        for (int kstep = 0; kstep < 2; kstep++) {
            const uint32_t kk = kstep * 32;
            uint32_t a[4][4], bh[2][4];
#pragma unroll
            for (int mt = 0; mt < 4; mt++)
                ldm_x4(a[mt][0], a[mt][1], a[mt][2], a[mt][3],
                       Ab + mt * (16 * 80) + kk);
#pragma unroll
            for (int ng = 0; ng < 2; ng++)
                ldm_x4(bh[ng][0], bh[ng][1], bh[ng][2], bh[ng][3],
                       Bb + ng * (16 * 80) + kk);
#pragma unroll
            for (int mt = 0; mt < 4; mt++)
#pragma unroll
                for (int nt = 0; nt < 4; nt++)
                    mma_bf16(acc[mt][nt],
                             a[mt][0], a[mt][1], a[mt][2], a[mt][3],
                             bh[nt >> 1][(nt & 1) * 2], bh[nt >> 1][(nt & 1) * 2 + 1]);
            if (pass1) {
                uint32_t bl[2][4];
#pragma unroll
                for (int ng = 0; ng < 2; ng++)
                    ldm_x4(bl[ng][0], bl[ng][1], bl[ng][2], bl[ng][3],
                           Bb + (SOFF_BL - SOFF_BH) + ng * (16 * 80) + kk);
#pragma unroll
                for (int mt = 0; mt < 4; mt++)
#pragma unroll
                    for (int nt = 0; nt < 4; nt++)
                        mma_bf16(acc[mt][nt],
                                 a[mt][0], a[mt][1], a[mt][2], a[mt][3],
                                 bl[nt >> 1][(nt & 1) * 2], bl[nt >> 1][(nt & 1) * 2 + 1]);
            }
        }
    }

    // epilogue
    const int grp = lane >> 2, tig = lane & 3;
#pragma unroll
    for (int mt = 0; mt < 4; mt++) {
        int r = row0 + wm * 64 + mt * 16 + grp;
#pragma unroll
        for (int nt = 0; nt < 4; nt++) {
            int col = col0 + wn * 32 + nt * 8 + tig * 2;
            float b0 = p.bias[col], b1 = p.bias[col + 1];
            float2 lo, hi;
            lo.x = acc[mt][nt][0] + b0; lo.y = acc[mt][nt][1] + b1;
            hi.x = acc[mt][nt][2] + b0; hi.y = acc[mt][nt][3] + b1;
            *(float2*)(p.C + (size_t)r * p.ldc + col) = lo;
            *(float2*)(p.C + (size_t)(r + 8) * p.ldc + col) = hi;
        }
    }
}

struct B9 { const float* b[9]; };

// z = m*3 + t  (q/k/v of same modality adjacent: A stays L2-hot)
__global__ void __launch_bounds__(256, 2) qkv_gemm_kernel(B9 biases)
{
    const int colA[3] = {0, 2048, 2560};
    const int Kp[3]   = {2048, 512, 512};
    int z = blockIdx.z, m = z / 3, t = z - m * 3;
    GP p;
    p.Ah = g_ah; p.Al = g_al; p.ldA = APAD; p.colA = colA[m];
    p.Bh = g_wh + (size_t)t * 256 * APAD;
    p.Bl = g_wl + (size_t)t * 256 * APAD;
    p.ldB = APAD; p.colB = colA[m];
    p.Kp = Kp[m];
    p.bias = biases.b[t * 3 + m];
    p.C = ((t == 0) ? g_q : (t == 1) ? g_k : g_v) + m * 256;
    p.ldc = QKV_LD;
    gemm_body(p);
}

__global__ void __launch_bounds__(256, 2) fc_gemm_kernel(const float* fc_b)
{
    GP p;
    p.Ah = g_oh; p.Al = g_ol; p.ldA = 256; p.colA = 0;
    p.Bh = g_fch; p.Bl = g_fcl; p.ldB = 256; p.colB = 0;
    p.Kp = 256;
    p.bias = fc_b; p.C = g_fc; p.ldc = 256;
    gemm_body(p);
}

// ------------- attention logits + global min ---------------------------------
__global__ void __launch_bounds__(256) attn_logits_kernel()
{
    int t  = blockIdx.x * blockDim.x + threadIdx.x;
    int bs = t >> 3, h = t & 7;
    const float4* qb = (const float4*)(g_q + bs * QKV_LD + h * 32);
    const float4* kb = (const float4*)(g_k + bs * QKV_LD + h * 32);

    float4 kr[3][8];
#pragma unroll
    for (int n = 0; n < 3; n++)
#pragma unroll
        for (int j = 0; j < 8; j++) kr[n][j] = kb[n * 64 + j];

    float lmin = 3.4e38f;
#pragma unroll
    for (int m = 0; m < 3; m++) {
        float4 qv[8];
#pragma unroll
        for (int j = 0; j < 8; j++) qv[j] = qb[m * 64 + j];
#pragma unroll
        for (int n = 0; n < 3; n++) {
            float s = 0.f;
#pragma unroll
            for (int j = 0; j < 8; j++) {
                s = fmaf(qv[j].x, kr[n][j].x, s);
                s = fmaf(qv[j].y, kr[n][j].y, s);
                s = fmaf(qv[j].z, kr[n][j].z, s);
                s = fmaf(qv[j].w, kr[n][j].w, s);
            }
            s *= TEMP_INV;
            g_logits[t * 9 + m * 3 + n] = s;
            lmin = fminf(lmin, s);
        }
    }
#pragma unroll
    for (int off = 16; off; off >>= 1)
        lmin = fminf(lmin, __shfl_xor_sync(0xFFFFFFFFu, lmin, off));
    if ((threadIdx.x & 31) == 0) atomicMin(&g_minkey, f2key(lmin));
}

// ------------- scale / L1 / softmax / PV --------------------------------------
__global__ void __launch_bounds__(256) attn_softmax_o_kernel()
{
    int t  = blockIdx.x * blockDim.x + threadIdx.x;
    int bs = t >> 3, h = t & 7;
    float inv = 1.0f / fabsf(key2f(g_minkey));

    const float* lg = g_logits + t * 9;
    const float4* vb = (const float4*)(g_v + bs * QKV_LD + h * 32);
    float* ob = g_o + bs * QKV_LD + h * 32;

#pragma unroll
    for (int m = 0; m < 3; m++) {
        float r0 = lg[m*3+0]*inv, r1 = lg[m*3+1]*inv, r2 = lg[m*3+2]*inv;
        float l1 = fmaxf(fabsf(r0) + fabsf(r1) + fabsf(r2), 1e-12f);
        r0 /= l1; r1 /= l1; r2 /= l1;
        float mx = fmaxf(r0, fmaxf(r1, r2));
        float e0 = expf(r0-mx), e1 = expf(r1-mx), e2 = expf(r2-mx);
        float es = e0 + e1 + e2;
        float p0 = e0/es, p1 = e1/es, p2 = e2/es;

        float4* o4 = (float4*)(ob + m * 256);
#pragma unroll
        for (int j = 0; j < 8; j++) {
            float4 v0 = vb[j], v1 = vb[64+j], v2 = vb[128+j];
            float4 r;
            r.x = p0*v0.x + p1*v1.x + p2*v2.x;
            r.y = p0*v0.y + p1*v1.y + p2*v2.y;
            r.z = p0*v0.z + p1*v1.z + p2*v2.z;
            r.w = p0*v0.w + p1*v1.w + p2*v2.w;
            o4[j] = r;
        }
    }
}

// ------------- residual + layernorm -------------------------------------------
__global__ void __launch_bounds__(256) ln_kernel(
    const float* __restrict__ ln_g, const float* __restrict__ ln_b)
{
    int row  = blockIdx.x * 8 + (threadIdx.x >> 5);
    int lane = threadIdx.x & 31;
    const float* fr = g_fc + (size_t)row * 256;
    const float* vr = g_v  + (size_t)row * 256;

    float x[8];
#pragma unroll
    for (int i = 0; i < 8; i++) x[i] = fr[lane + i*32] + vr[lane + i*32];

    float s = 0.f;
#pragma unroll
    for (int i = 0; i < 8; i++) s += x[i];
#pragma unroll
    for (int off = 16; off; off >>= 1) s += __shfl_xor_sync(0xFFFFFFFFu, s, off);
    float mu = s * (1.0f/256.0f);

    float ss = 0.f;
#pragma unroll
    for (int i = 0; i < 8; i++) { float d = x[i]-mu; ss += d*d; }
#pragma unroll
    for (int off = 16; off; off >>= 1) ss += __shfl_xor_sync(0xFFFFFFFFu, ss, off);
    float rstd = rsqrtf(ss * (1.0f/256.0f) + LN_EPS);

    float* xr = g_x + (size_t)row * 256;
#pragma unroll
    for (int i = 0; i < 8; i++) {
        int idx = lane + i*32;
        xr[idx] = (x[i]-mu)*rstd*ln_g[idx] + ln_b[idx];
    }
}

// ------------- final skinny GEMM [BS,768] @ [768,5] ---------------------------
__global__ void __launch_bounds__(256) out_kernel(
    const float* __restrict__ out_w, const float* __restrict__ out_b,
    float* __restrict__ out)
{
    __shared__ float sw[768 * 5];
    for (int i = threadIdx.x; i < 768*5; i += 256) sw[i] = out_w[i];
    __syncthreads();

    int samp = blockIdx.x * 8 + (threadIdx.x >> 5);
    int lane = threadIdx.x & 31;
    const float* xr = g_x + (size_t)samp * 768;

    float acc[5] = {0.f, 0.f, 0.f, 0.f, 0.f};
    for (int i = lane; i < 768; i += 32) {
        float xv = xr[i];
#pragma unroll
        for (int c = 0; c < 5; c++) acc[c] = fmaf(xv, sw[i*5+c], acc[c]);
    }
#pragma unroll
    for (int off = 16; off; off >>= 1)
#pragma unroll
        for (int c = 0; c < 5; c++)
            acc[c] += __shfl_xor_sync(0xFFFFFFFFu, acc[c], off);

    if (lane < 5) out[samp*5 + lane] = acc[lane] + out_b[lane];
}

// ==============================================================================
extern "C" void kernel_launch(void* const* d_in, const int* in_sizes, int n_in,
                              void* d_out, int out_size)
{
    const float* X = (const float*)d_in[0];
    W9 ws; B9 bs;
    for (int t = 0; t < 3; t++)
        for (int m = 0; m < 3; m++) {
            ws.w[t*3+m] = (const float*)d_in[1 + t*6 + m*2];
            bs.b[t*3+m] = (const float*)d_in[2 + t*6 + m*2];
        }
    const float* fc_w  = (const float*)d_in[19];
    const float* fc_b  = (const float*)d_in[20];
    const float* ln_g  = (const float*)d_in[21];
    const float* ln_b  = (const float*)d_in[22];
    const float* out_w = (const float*)d_in[23];
    const float* out_b = (const float*)d_in[24];
    float* out = (float*)d_out;

    static int smem_set = 0;
    if (!smem_set) {
        cudaFuncSetAttribute(qkv_gemm_kernel, cudaFuncAttributeMaxDynamicSharedMemorySize, SMEM_GEMM);
        cudaFuncSetAttribute(fc_gemm_kernel,  cudaFuncAttributeMaxDynamicSharedMemorySize, SMEM_GEMM);
        smem_set = 1;
    }

    init_min_kernel<<<1, 1>>>();                    // launch 0
    conv_x_kernel<<<dim3(6, BSZ), 256>>>(X);        // launch 1
    conv_w_kernel<<<dim3(1024, 1, 9), 256>>>(ws);   // launch 2
    conv_fcw_kernel<<<128, 256>>>(fc_w);            // launch 3
    noop_kernel<<<1, 32>>>();                       // launch 4 (ncu -s 5 spacer)

    qkv_gemm_kernel<<<dim3(2, BSZ/128, 9), 256, SMEM_GEMM>>>(bs);   // launch 5 -> profiled

    attn_logits_kernel<<<(BSZ*8)/256, 256>>>();
    attn_softmax_o_kernel<<<(BSZ*8)/256, 256>>>();

    conv_o_kernel<<<(NROWS*256/2)/256, 256>>>();
    fc_gemm_kernel<<<dim3(2, NROWS/128, 1), 256, SMEM_GEMM>>>(fc_b);

    ln_kernel<<<NROWS/8, 256>>>(ln_g, ln_b);
    out_kernel<<<BSZ/8, 256>>>(out_w, out_b, out);
}

// round 6
// speedup vs baseline: 3.0109x; 1.2359x over previous
#include <cuda_runtime.h>
#include <cuda_fp16.h>
#include <cstdint>

#define BSZ    16384
#define QKV_LD 768
#define NROWS  (BSZ*3)
#define LN_EPS 1e-6f
#define TEMP_INV 0.17677669529663687f
#define APAD   3072      // padded concat K: 2048 + 512 + 512

// ---------------- scratch (static device arrays; no cudaMalloc) --------------
__device__ __align__(16) float g_q [BSZ*QKV_LD];
__device__ __align__(16) float g_k [BSZ*QKV_LD];
__device__ __align__(16) float g_v [BSZ*QKV_LD];
__device__ __align__(16) float g_fc[BSZ*QKV_LD];
__device__ __align__(16) float g_logits[BSZ*8*9];
__device__ unsigned g_minkey;

__device__ __align__(16) __half g_ah[(size_t)BSZ*APAD];
__device__ __align__(16) __half g_al[(size_t)BSZ*APAD];
__device__ __align__(16) __half g_wh[(size_t)3*256*APAD];
__device__ __align__(16) __half g_oh[(size_t)NROWS*256];
__device__ __align__(16) __half g_ol[(size_t)NROWS*256];
__device__ __align__(16) __half g_fch[256*256];

// ---------------- small helpers ----------------------------------------------
__device__ __forceinline__ unsigned f2key(float f) {
    unsigned u = __float_as_uint(f);
    return (u & 0x80000000u) ? ~u : (u | 0x80000000u);
}
__device__ __forceinline__ float key2f(unsigned k) {
    unsigned u = (k & 0x80000000u) ? (k & 0x7FFFFFFFu) : ~k;
    return __uint_as_float(u);
}
__global__ void init_min_kernel() { g_minkey = 0xFFFFFFFFu; }
__global__ void noop_kernel() {}

__device__ __forceinline__ uint32_t su32(const void* p) {
    return (uint32_t)__cvta_generic_to_shared(p);
}
__device__ __forceinline__ void cp16(uint32_t dst, const void* src) {
    asm volatile("cp.async.cg.shared.global [%0], [%1], 16;"
                 :: "r"(dst), "l"(src) : "memory");
}
__device__ __forceinline__ void cp_commit() {
    asm volatile("cp.async.commit_group;" ::: "memory");
}
__device__ __forceinline__ void ldm_x4(uint32_t& r0, uint32_t& r1, uint32_t& r2,
                                       uint32_t& r3, uint32_t addr) {
    asm volatile("ldmatrix.sync.aligned.m8n8.x4.shared.b16 {%0,%1,%2,%3}, [%4];"
                 : "=r"(r0), "=r"(r1), "=r"(r2), "=r"(r3) : "r"(addr));
}
__device__ __forceinline__ void mma_f16(float* c, uint32_t a0, uint32_t a1,
                                        uint32_t a2, uint32_t a3,
                                        uint32_t b0, uint32_t b1) {
    asm volatile(
        "mma.sync.aligned.m16n8k16.row.col.f32.f16.f16.f32 "
        "{%0,%1,%2,%3}, {%4,%5,%6,%7}, {%8,%9}, {%0,%1,%2,%3};"
        : "+f"(c[0]), "+f"(c[1]), "+f"(c[2]), "+f"(c[3])
        : "r"(a0), "r"(a1), "r"(a2), "r"(a3), "r"(b0), "r"(b1));
}
__device__ __forceinline__ void split_f16(float v, __half& h, __half& l) {
    h = __float2half(v);
    l = __float2half(v - __half2float(h));
}

// ---------------- conversion kernels -----------------------------------------
__global__ void __launch_bounds__(256) conv_x_kernel(const float* __restrict__ X)
{
    int col2 = (blockIdx.x * 256 + threadIdx.x) * 2;
    int row  = blockIdx.y;
    __half h[2], l[2];
#pragma unroll
    for (int e = 0; e < 2; e++) {
        int col = col2 + e;
        float x = 0.f;
        if (col < 2048)      { if (col < 2000) x = X[(size_t)row*2900 + col]; }
        else if (col < 2560) { int c = col-2048; if (c < 500) x = X[(size_t)row*2900 + 2000 + c]; }
        else                 { int c = col-2560; if (c < 400) x = X[(size_t)row*2900 + 2500 + c]; }
        split_f16(x, h[e], l[e]);
    }
    __half2 hh; hh.x = h[0]; hh.y = h[1];
    __half2 ll; ll.x = l[0]; ll.y = l[1];
    *(__half2*)&g_ah[(size_t)row*APAD + col2] = hh;
    *(__half2*)&g_al[(size_t)row*APAD + col2] = ll;
}

struct W9 { const float* w[9]; };
__global__ void __launch_bounds__(256) conv_w_kernel(W9 ws)
{
    const int Km[3]   = {2000, 500, 400};
    const int Kp[3]   = {2048, 512, 512};
    const int colA[3] = {0, 2048, 2560};
    int z = blockIdx.z, t = z / 3, m = z - t * 3;
    int idx = (blockIdx.x * 256 + threadIdx.x) * 2;
    if (idx >= 256 * Kp[m]) return;
    int n  = idx / Kp[m];
    int kp = idx - n * Kp[m];
    const float* W = ws.w[z];
    float x0 = (kp     < Km[m]) ? W[(size_t)kp*256 + n]     : 0.f;
    float x1 = (kp + 1 < Km[m]) ? W[(size_t)(kp+1)*256 + n] : 0.f;
    __half2 hh; hh.x = __float2half(x0); hh.y = __float2half(x1);
    size_t o = (size_t)t*256*APAD + (size_t)n*APAD + colA[m] + kp;
    *(__half2*)&g_wh[o] = hh;
}

__global__ void __launch_bounds__(256) conv_fcw_kernel(const float* __restrict__ fcw)
{
    int idx = (blockIdx.x * 256 + threadIdx.x) * 2;
    int n = idx >> 8, k = idx & 255;
    __half2 hh;
    hh.x = __float2half(fcw[(size_t)k*256 + n]);
    hh.y = __float2half(fcw[(size_t)(k+1)*256 + n]);
    *(__half2*)&g_fch[n*256 + k] = hh;
}

// ---------------- mma.sync split-fp16 GEMM -------------------------------------
// C[M,256] = (Ah+Al)[M,K] @ Bh[256,K]-rows + bias  (2-product fp16 split)
struct GP {
    const __half *Ah, *Al, *B;
    int ldA, ldB, colA, colB, Kp;
    const float* bias;
    float* C; int ldc;
};

// stage: A 128x80B + B 128x80B  (K-chunk 32, 80B padded rows)
#define SOFF_B 10240
#define SSTG   20480
#define SMEM_GEMM (3*SSTG)   // 61440 -> 2 CTAs/SM

__device__ __forceinline__ void gemm_body(const GP p)
{
    extern __shared__ __align__(16) char dsm[];
    const int tid  = threadIdx.x;
    const int lane = tid & 31, wid = tid >> 5;
    const int wm = wid >> 2, wn = wid & 3;            // 2x4 warp grid
    const int row0 = blockIdx.y * 128, col0 = blockIdx.x * 128;
    const uint32_t sbase = su32(dsm);

    const int ck = p.Kp >> 5;          // K=32 chunks per segment
    const int nchunk = 2 * ck;         // pass1 (Ah) + pass2 (Al)

    auto load_chunk = [&](int c) {
        int seg = (c >= ck);
        int kc  = seg ? c - ck : c;
        const __half* A  = seg ? p.Al : p.Ah;
        const __half* As = A + (size_t)row0 * p.ldA + p.colA + kc * 32;
        const __half* Bs = p.B + (size_t)col0 * p.ldB + p.colB + kc * 32;
        uint32_t Sd = sbase + (c % 3) * SSTG;
#pragma unroll
        for (int i = 0; i < 2; i++) {
            int id = i * 256 + tid, r = id >> 2, kg = id & 3;
            cp16(Sd + r * 80 + kg * 16, As + (size_t)r * p.ldA + kg * 8);
            cp16(Sd + SOFF_B + r * 80 + kg * 16, Bs + (size_t)r * p.ldB + kg * 8);
        }
    };

    float acc[4][4][4];
#pragma unroll
    for (int i = 0; i < 4; i++)
#pragma unroll
        for (int j = 0; j < 4; j++)
#pragma unroll
            for (int r = 0; r < 4; r++) acc[i][j][r] = 0.f;

    load_chunk(0); cp_commit();

    // per-lane ldmatrix byte offsets (80B smem row stride)
    const uint32_t a_off = (uint32_t)((wm * 64 + (lane & 15)) * 80 + ((lane >> 4) << 4));
    const uint32_t b_off = (uint32_t)((wn * 32 + (lane & 7) + ((lane & 16) >> 1)) * 80
                                      + ((lane & 8) << 1));

    for (int c = 0; c < nchunk; c++) {
        if (c + 1 < nchunk) {
            load_chunk(c + 1); cp_commit();
            asm volatile("cp.async.wait_group 1;" ::: "memory");
        } else {
            asm volatile("cp.async.wait_group 0;" ::: "memory");
        }
        __syncthreads();

        const uint32_t Sd = sbase + (c % 3) * SSTG;
        const uint32_t Ab = Sd + a_off;
        const uint32_t Bb = Sd + SOFF_B + b_off;
#pragma unroll
        for (int kstep = 0; kstep < 2; kstep++) {
            const uint32_t kk = kstep * 32;
            uint32_t a[4][4], b[2][4];
#pragma unroll
            for (int mt = 0; mt < 4; mt++)
                ldm_x4(a[mt][0], a[mt][1], a[mt][2], a[mt][3],
                       Ab + mt * (16 * 80) + kk);
#pragma unroll
            for (int ng = 0; ng < 2; ng++)
                ldm_x4(b[ng][0], b[ng][1], b[ng][2], b[ng][3],
                       Bb + ng * (16 * 80) + kk);
#pragma unroll
            for (int mt = 0; mt < 4; mt++)
#pragma unroll
                for (int nt = 0; nt < 4; nt++)
                    mma_f16(acc[mt][nt],
                            a[mt][0], a[mt][1], a[mt][2], a[mt][3],
                            b[nt >> 1][(nt & 1) * 2], b[nt >> 1][(nt & 1) * 2 + 1]);
        }
    }

    // epilogue
    const int grp = lane >> 2, tig = lane & 3;
#pragma unroll
    for (int mt = 0; mt < 4; mt++) {
        int r = row0 + wm * 64 + mt * 16 + grp;
#pragma unroll
        for (int nt = 0; nt < 4; nt++) {
            int col = col0 + wn * 32 + nt * 8 + tig * 2;
            float b0 = p.bias[col], b1 = p.bias[col + 1];
            float2 lo, hi;
            lo.x = acc[mt][nt][0] + b0; lo.y = acc[mt][nt][1] + b1;
            hi.x = acc[mt][nt][2] + b0; hi.y = acc[mt][nt][3] + b1;
            *(float2*)(p.C + (size_t)r * p.ldc + col) = lo;
            *(float2*)(p.C + (size_t)(r + 8) * p.ldc + col) = hi;
        }
    }
}

struct B9 { const float* b[9]; };

// z = m*3 + t  (q/k/v of same modality adjacent: A stays L2-hot)
__global__ void __launch_bounds__(256, 2) qkv_gemm_kernel(B9 biases)
{
    const int colA[3] = {0, 2048, 2560};
    const int Kp[3]   = {2048, 512, 512};
    int z = blockIdx.z, m = z / 3, t = z - m * 3;
    GP p;
    p.Ah = g_ah; p.Al = g_al; p.ldA = APAD; p.colA = colA[m];
    p.B  = g_wh + (size_t)t * 256 * APAD;
    p.ldB = APAD; p.colB = colA[m];
    p.Kp = Kp[m];
    p.bias = biases.b[t * 3 + m];
    p.C = ((t == 0) ? g_q : (t == 1) ? g_k : g_v) + m * 256;
    p.ldc = QKV_LD;
    gemm_body(p);
}

__global__ void __launch_bounds__(256, 2) fc_gemm_kernel(const float* fc_b)
{
    GP p;
    p.Ah = g_oh; p.Al = g_ol; p.ldA = 256; p.colA = 0;
    p.B  = g_fch; p.ldB = 256; p.colB = 0;
    p.Kp = 256;
    p.bias = fc_b; p.C = g_fc; p.ldc = 256;
    gemm_body(p);
}

// ------------- attention logits + global min ---------------------------------
__global__ void __launch_bounds__(256) attn_logits_kernel()
{
    int t  = blockIdx.x * blockDim.x + threadIdx.x;
    int bs = t >> 3, h = t & 7;
    const float4* qb = (const float4*)(g_q + bs * QKV_LD + h * 32);
    const float4* kb = (const float4*)(g_k + bs * QKV_LD + h * 32);

    float4 kr[3][8];
#pragma unroll
    for (int n = 0; n < 3; n++)
#pragma unroll
        for (int j = 0; j < 8; j++) kr[n][j] = kb[n * 64 + j];

    float lmin = 3.4e38f;
#pragma unroll
    for (int m = 0; m < 3; m++) {
        float4 qv[8];
#pragma unroll
        for (int j = 0; j < 8; j++) qv[j] = qb[m * 64 + j];
#pragma unroll
        for (int n = 0; n < 3; n++) {
            float s = 0.f;
#pragma unroll
            for (int j = 0; j < 8; j++) {
                s = fmaf(qv[j].x, kr[n][j].x, s);
                s = fmaf(qv[j].y, kr[n][j].y, s);
                s = fmaf(qv[j].z, kr[n][j].z, s);
                s = fmaf(qv[j].w, kr[n][j].w, s);
            }
            s *= TEMP_INV;
            g_logits[t * 9 + m * 3 + n] = s;
            lmin = fminf(lmin, s);
        }
    }
#pragma unroll
    for (int off = 16; off; off >>= 1)
        lmin = fminf(lmin, __shfl_xor_sync(0xFFFFFFFFu, lmin, off));
    if ((threadIdx.x & 31) == 0) atomicMin(&g_minkey, f2key(lmin));
}

// ------------- scale / L1 / softmax / PV -> fp16 hi/lo o ----------------------
__global__ void __launch_bounds__(256) attn_softmax_o_kernel()
{
    int t  = blockIdx.x * blockDim.x + threadIdx.x;
    int bs = t >> 3, h = t & 7;
    float inv = 1.0f / fabsf(key2f(g_minkey));

    const float* lg = g_logits + t * 9;
    const float4* vb = (const float4*)(g_v + bs * QKV_LD + h * 32);
    size_t obase = (size_t)bs * QKV_LD + h * 32;

#pragma unroll
    for (int m = 0; m < 3; m++) {
        float r0 = lg[m*3+0]*inv, r1 = lg[m*3+1]*inv, r2 = lg[m*3+2]*inv;
        float l1 = fmaxf(fabsf(r0) + fabsf(r1) + fabsf(r2), 1e-12f);
        r0 /= l1; r1 /= l1; r2 /= l1;
        float mx = fmaxf(r0, fmaxf(r1, r2));
        float e0 = expf(r0-mx), e1 = expf(r1-mx), e2 = expf(r2-mx);
        float es = e0 + e1 + e2;
        float p0 = e0/es, p1 = e1/es, p2 = e2/es;

        __half2* oh2 = (__half2*)&g_oh[obase + m * 256];
        __half2* ol2 = (__half2*)&g_ol[obase + m * 256];
#pragma unroll
        for (int j = 0; j < 8; j++) {
            float4 v0 = vb[j], v1 = vb[64+j], v2 = vb[128+j];
            float r[4];
            r[0] = p0*v0.x + p1*v1.x + p2*v2.x;
            r[1] = p0*v0.y + p1*v1.y + p2*v2.y;
            r[2] = p0*v0.z + p1*v1.z + p2*v2.z;
            r[3] = p0*v0.w + p1*v1.w + p2*v2.w;
            __half hh[4], ll[4];
#pragma unroll
            for (int e = 0; e < 4; e++) split_f16(r[e], hh[e], ll[e]);
            __half2 h01; h01.x = hh[0]; h01.y = hh[1];
            __half2 h23; h23.x = hh[2]; h23.y = hh[3];
            __half2 l01; l01.x = ll[0]; l01.y = ll[1];
            __half2 l23; l23.x = ll[2]; l23.y = ll[3];
            oh2[j*2]   = h01; oh2[j*2+1] = h23;
            ol2[j*2]   = l01; ol2[j*2+1] = l23;
        }
    }
}

// ------------- fused residual + layernorm + out GEMM --------------------------
// one block per sample: 3 rows of 256 -> LN each -> dot with out_w[768,5]
__global__ void __launch_bounds__(256) ln_out_kernel(
    const float* __restrict__ ln_g, const float* __restrict__ ln_b,
    const float* __restrict__ out_w, const float* __restrict__ out_b,
    float* __restrict__ out)
{
    __shared__ float red[8][8];
    __shared__ float bcast[8];

    int s = blockIdx.x, tid = threadIdx.x;
    int lane = tid & 31, wid = tid >> 5;

    float x[3];
#pragma unroll
    for (int m = 0; m < 3; m++) {
        size_t r = (size_t)(s * 3 + m) * 256 + tid;
        x[m] = g_fc[r] + g_v[r];
    }

    float v6[6] = {x[0], x[1], x[2], x[0]*x[0], x[1]*x[1], x[2]*x[2]};
#pragma unroll
    for (int off = 16; off; off >>= 1)
#pragma unroll
        for (int i = 0; i < 6; i++)
            v6[i] += __shfl_xor_sync(0xFFFFFFFFu, v6[i], off);
    if (lane < 6) red[wid][lane] = v6[lane];
    __syncthreads();
    if (wid == 0) {
#pragma unroll
        for (int i = 0; i < 6; i++) {
            float t = (lane < 8) ? red[lane][i] : 0.f;
#pragma unroll
            for (int off = 4; off; off >>= 1)
                t += __shfl_xor_sync(0xFFFFFFFFu, t, off);
            if (lane == 0) bcast[i] = t;
        }
    }
    __syncthreads();

    float gg = ln_g[tid], bb = ln_b[tid];
    float acc[5] = {0.f, 0.f, 0.f, 0.f, 0.f};
#pragma unroll
    for (int m = 0; m < 3; m++) {
        float mu  = bcast[m] * (1.0f / 256.0f);
        float var = bcast[m + 3] * (1.0f / 256.0f) - mu * mu;
        float rstd = rsqrtf(var + LN_EPS);
        float xn = (x[m] - mu) * rstd * gg + bb;
        const float* wrow = out_w + (size_t)(m * 256 + tid) * 5;
#pragma unroll
        for (int c = 0; c < 5; c++) acc[c] = fmaf(xn, wrow[c], acc[c]);
    }
#pragma unroll
    for (int off = 16; off; off >>= 1)
#pragma unroll
        for (int c = 0; c < 5; c++)
            acc[c] += __shfl_xor_sync(0xFFFFFFFFu, acc[c], off);
    if (lane < 5) red[wid][lane] = acc[lane];
    __syncthreads();
    if (wid == 0 && lane < 5) {
        float t = 0.f;
#pragma unroll
        for (int w = 0; w < 8; w++) t += red[w][lane];
        out[s * 5 + lane] = t + out_b[lane];
    }
}

// ==============================================================================
extern "C" void kernel_launch(void* const* d_in, const int* in_sizes, int n_in,
                              void* d_out, int out_size)
{
    const float* X = (const float*)d_in[0];
    W9 ws; B9 bs;
    for (int t = 0; t < 3; t++)
        for (int m = 0; m < 3; m++) {
            ws.w[t*3+m] = (const float*)d_in[1 + t*6 + m*2];
            bs.b[t*3+m] = (const float*)d_in[2 + t*6 + m*2];
        }
    const float* fc_w  = (const float*)d_in[19];
    const float* fc_b  = (const float*)d_in[20];
    const float* ln_g  = (const float*)d_in[21];
    const float* ln_b  = (const float*)d_in[22];
    const float* out_w = (const float*)d_in[23];
    const float* out_b = (const float*)d_in[24];
    float* out = (float*)d_out;

    static int smem_set = 0;
    if (!smem_set) {
        cudaFuncSetAttribute(qkv_gemm_kernel, cudaFuncAttributeMaxDynamicSharedMemorySize, SMEM_GEMM);
        cudaFuncSetAttribute(fc_gemm_kernel,  cudaFuncAttributeMaxDynamicSharedMemorySize, SMEM_GEMM);
        smem_set = 1;
    }

    init_min_kernel<<<1, 1>>>();                    // 0
    conv_x_kernel<<<dim3(6, BSZ), 256>>>(X);        // 1
    conv_w_kernel<<<dim3(1024, 1, 9), 256>>>(ws);   // 2
    conv_fcw_kernel<<<128, 256>>>(fc_w);            // 3
    noop_kernel<<<1, 32>>>();                       // 4

    qkv_gemm_kernel<<<dim3(2, BSZ/128, 9), 256, SMEM_GEMM>>>(bs);  // 5

    attn_logits_kernel<<<(BSZ*8)/256, 256>>>();
    attn_softmax_o_kernel<<<(BSZ*8)/256, 256>>>();

    fc_gemm_kernel<<<dim3(2, NROWS/128, 1), 256, SMEM_GEMM>>>(fc_b);

    ln_out_kernel<<<BSZ, 256>>>(ln_g, ln_b, out_w, out_b, out);
}

// round 7
// speedup vs baseline: 3.0933x; 1.0274x over previous
#include <cuda_runtime.h>
#include <cuda_fp16.h>
#include <cstdint>

#define BSZ    16384
#define QKV_LD 768
#define NROWS  (BSZ*3)
#define LN_EPS 1e-6f
#define TEMP_INV 0.17677669529663687f
#define APAD   3072      // A layout stride; used cols = 2016+512+416 = 2944

// ---------------- scratch (static device arrays; no cudaMalloc) --------------
__device__ __align__(16) float g_q [BSZ*QKV_LD];
__device__ __align__(16) float g_k [BSZ*QKV_LD];
__device__ __align__(16) float g_v [BSZ*QKV_LD];
__device__ __align__(16) float g_fc[BSZ*QKV_LD];
__device__ __align__(16) float g_logits[BSZ*8*9];
__device__ unsigned g_minkey;

__device__ __align__(16) __half g_ah[(size_t)BSZ*APAD];
__device__ __align__(16) __half g_al[(size_t)BSZ*APAD];
__device__ __align__(16) __half g_wh[(size_t)3*256*APAD];
__device__ __align__(16) __half g_oh[(size_t)NROWS*256];
__device__ __align__(16) __half g_ol[(size_t)NROWS*256];
__device__ __align__(16) __half g_fch[256*256];

// ---------------- small helpers ----------------------------------------------
__device__ __forceinline__ unsigned f2key(float f) {
    unsigned u = __float_as_uint(f);
    return (u & 0x80000000u) ? ~u : (u | 0x80000000u);
}
__device__ __forceinline__ float key2f(unsigned k) {
    unsigned u = (k & 0x80000000u) ? (k & 0x7FFFFFFFu) : ~k;
    return __uint_as_float(u);
}
__global__ void init_min_kernel() { g_minkey = 0xFFFFFFFFu; }

__device__ __forceinline__ uint32_t su32(const void* p) {
    return (uint32_t)__cvta_generic_to_shared(p);
}
__device__ __forceinline__ void cp16(uint32_t dst, const void* src) {
    asm volatile("cp.async.cg.shared.global [%0], [%1], 16;"
                 :: "r"(dst), "l"(src) : "memory");
}
__device__ __forceinline__ void cp_commit() {
    asm volatile("cp.async.commit_group;" ::: "memory");
}
__device__ __forceinline__ void ldm_x4(uint32_t& r0, uint32_t& r1, uint32_t& r2,
                                       uint32_t& r3, uint32_t addr) {
    asm volatile("ldmatrix.sync.aligned.m8n8.x4.shared.b16 {%0,%1,%2,%3}, [%4];"
                 : "=r"(r0), "=r"(r1), "=r"(r2), "=r"(r3) : "r"(addr));
}
__device__ __forceinline__ void mma_f16(float* c, uint32_t a0, uint32_t a1,
                                        uint32_t a2, uint32_t a3,
                                        uint32_t b0, uint32_t b1) {
    asm volatile(
        "mma.sync.aligned.m16n8k16.row.col.f32.f16.f16.f32 "
        "{%0,%1,%2,%3}, {%4,%5,%6,%7}, {%8,%9}, {%0,%1,%2,%3};"
        : "+f"(c[0]), "+f"(c[1]), "+f"(c[2]), "+f"(c[3])
        : "r"(a0), "r"(a1), "r"(a2), "r"(a3), "r"(b0), "r"(b1));
}
__device__ __forceinline__ void split_f16(float v, __half& h, __half& l) {
    h = __float2half(v);
    l = __float2half(v - __half2float(h));
}

// ---------------- conversion kernels -----------------------------------------
// padded segments: [0,2016) <- X[0,2000); [2016,2528) <- X[2000,2500); [2528,2944) <- X[2500,2900)
__global__ void __launch_bounds__(256) conv_x_kernel(const float* __restrict__ X)
{
    int col2 = (blockIdx.x * 256 + threadIdx.x) * 2;
    int row  = blockIdx.y;
    __half h[2], l[2];
#pragma unroll
    for (int e = 0; e < 2; e++) {
        int col = col2 + e;
        float x = 0.f;
        if (col < 2016)      { if (col < 2000) x = X[(size_t)row*2900 + col]; }
        else if (col < 2528) { int c = col-2016; if (c < 500) x = X[(size_t)row*2900 + 2000 + c]; }
        else                 { int c = col-2528; if (c < 400) x = X[(size_t)row*2900 + 2500 + c]; }
        split_f16(x, h[e], l[e]);
    }
    __half2 hh; hh.x = h[0]; hh.y = h[1];
    __half2 ll; ll.x = l[0]; ll.y = l[1];
    *(__half2*)&g_ah[(size_t)row*APAD + col2] = hh;
    *(__half2*)&g_al[(size_t)row*APAD + col2] = ll;
}

struct W9 { const float* w[9]; };
__global__ void __launch_bounds__(256) conv_w_kernel(W9 ws)
{
    const int Km[3]   = {2000, 500, 400};
    const int Kp[3]   = {2016, 512, 416};
    const int colA[3] = {0, 2016, 2528};
    int z = blockIdx.z, t = z / 3, m = z - t * 3;
    int idx = (blockIdx.x * 256 + threadIdx.x) * 2;
    if (idx >= 256 * Kp[m]) return;
    int n  = idx / Kp[m];
    int kp = idx - n * Kp[m];
    const float* W = ws.w[z];
    float x0 = (kp     < Km[m]) ? W[(size_t)kp*256 + n]     : 0.f;
    float x1 = (kp + 1 < Km[m]) ? W[(size_t)(kp+1)*256 + n] : 0.f;
    __half2 hh; hh.x = __float2half(x0); hh.y = __float2half(x1);
    size_t o = (size_t)t*256*APAD + (size_t)n*APAD + colA[m] + kp;
    *(__half2*)&g_wh[o] = hh;
}

__global__ void __launch_bounds__(256) conv_fcw_kernel(const float* __restrict__ fcw)
{
    int idx = (blockIdx.x * 256 + threadIdx.x) * 2;
    int n = idx >> 8, k = idx & 255;
    __half2 hh;
    hh.x = __float2half(fcw[(size_t)k*256 + n]);
    hh.y = __float2half(fcw[(size_t)(k+1)*256 + n]);
    *(__half2*)&g_fch[n*256 + k] = hh;
}

// ---------------- mma.sync split-fp16 GEMM -------------------------------------
// C[M,256] = (Ah+Al)[M,K] @ B[256,K]-rows + bias  (2-product fp16 split)
struct GP {
    const __half *Ah, *Al, *B;
    int ldA, ldB, colA, colB, Kp;
    const float* bias;
    float* C; int ldc;
};

// stage: A 128x80B + B 128x80B  (K-chunk 32, 80B padded rows); 5 stages
#define SOFF_B 10240
#define SSTG   20480
#define NSTAGE 5
#define SMEM_GEMM (NSTAGE*SSTG)   // 102400 -> 2 CTAs/SM (200KB)

__device__ __forceinline__ void gemm_body(const GP p)
{
    extern __shared__ __align__(16) char dsm[];
    const int tid  = threadIdx.x;
    const int lane = tid & 31, wid = tid >> 5;
    const int wm = wid >> 2, wn = wid & 3;            // 2x4 warp grid
    const int row0 = blockIdx.y * 128, col0 = blockIdx.x * 128;
    const uint32_t sbase = su32(dsm);

    const int ck = p.Kp >> 5;          // K=32 chunks per segment
    const int nchunk = 2 * ck;         // pass1 (Ah) + pass2 (Al)

    auto load_chunk = [&](int c, int buf) {
        int seg = (c >= ck);
        int kc  = seg ? c - ck : c;
        const __half* A  = seg ? p.Al : p.Ah;
        const __half* As = A + (size_t)row0 * p.ldA + p.colA + kc * 32;
        const __half* Bs = p.B + (size_t)col0 * p.ldB + p.colB + kc * 32;
        uint32_t Sd = sbase + buf * SSTG;
#pragma unroll
        for (int i = 0; i < 2; i++) {
            int id = i * 256 + tid, r = id >> 2, kg = id & 3;
            cp16(Sd + r * 80 + kg * 16, As + (size_t)r * p.ldA + kg * 8);
            cp16(Sd + SOFF_B + r * 80 + kg * 16, Bs + (size_t)r * p.ldB + kg * 8);
        }
    };

    float acc[4][4][4];
#pragma unroll
    for (int i = 0; i < 4; i++)
#pragma unroll
        for (int j = 0; j < 4; j++)
#pragma unroll
            for (int r = 0; r < 4; r++) acc[i][j][r] = 0.f;

    // preload chunks 0..2 into buffers 0..2 (3 commit groups)
    load_chunk(0, 0); cp_commit();
    load_chunk(1, 1); cp_commit();
    load_chunk(2, 2); cp_commit();

    // per-lane ldmatrix byte offsets (80B smem row stride)
    const uint32_t a_off = (uint32_t)((wm * 64 + (lane & 15)) * 80 + ((lane >> 4) << 4));
    const uint32_t b_off = (uint32_t)((wn * 32 + (lane & 7) + ((lane & 16) >> 1)) * 80
                                      + ((lane & 8) << 1));

    int bufc = 0;                       // buffer holding chunk c
    for (int c = 0; c < nchunk; c++) {
        // issue chunk c+3 into buffer (c+3)%5 == (c-2)%5; its readers (chunk c-2)
        // are fenced by the previous iteration's __syncthreads -> WAR-safe.
        int bnew = bufc + 3; if (bnew >= NSTAGE) bnew -= NSTAGE;
        if (c + 3 < nchunk) load_chunk(c + 3, bnew);
        cp_commit();                    // committed groups so far: c + 4
        asm volatile("cp.async.wait_group 3;" ::: "memory");  // chunk c resident
        __syncthreads();

        const uint32_t Sd = sbase + bufc * SSTG;
        const uint32_t Ab = Sd + a_off;
        const uint32_t Bb = Sd + SOFF_B + b_off;
#pragma unroll
        for (int kstep = 0; kstep < 2; kstep++) {
            const uint32_t kk = kstep * 32;
            uint32_t a[4][4], b[2][4];
#pragma unroll
            for (int mt = 0; mt < 4; mt++)
                ldm_x4(a[mt][0], a[mt][1], a[mt][2], a[mt][3],
                       Ab + mt * (16 * 80) + kk);
#pragma unroll
            for (int ng = 0; ng < 2; ng++)
                ldm_x4(b[ng][0], b[ng][1], b[ng][2], b[ng][3],
                       Bb + ng * (16 * 80) + kk);
#pragma unroll
            for (int mt = 0; mt < 4; mt++)
#pragma unroll
                for (int nt = 0; nt < 4; nt++)
                    mma_f16(acc[mt][nt],
                            a[mt][0], a[mt][1], a[mt][2], a[mt][3],
                            b[nt >> 1][(nt & 1) * 2], b[nt >> 1][(nt & 1) * 2 + 1]);
        }
        bufc++; if (bufc == NSTAGE) bufc = 0;
    }

    // epilogue
    const int grp = lane >> 2, tig = lane & 3;
#pragma unroll
    for (int mt = 0; mt < 4; mt++) {
        int r = row0 + wm * 64 + mt * 16 + grp;
#pragma unroll
        for (int nt = 0; nt < 4; nt++) {
            int col = col0 + wn * 32 + nt * 8 + tig * 2;
            float b0 = p.bias[col], b1 = p.bias[col + 1];
            float2 lo, hi;
            lo.x = acc[mt][nt][0] + b0; lo.y = acc[mt][nt][1] + b1;
            hi.x = acc[mt][nt][2] + b0; hi.y = acc[mt][nt][3] + b1;
            *(float2*)(p.C + (size_t)r * p.ldc + col) = lo;
            *(float2*)(p.C + (size_t)(r + 8) * p.ldc + col) = hi;
        }
    }
}

struct B9 { const float* b[9]; };

// z = m*3 + t  (q/k/v of same modality adjacent: A stays L2-hot)
__global__ void __launch_bounds__(256, 2) qkv_gemm_kernel(B9 biases)
{
    const int colA[3] = {0, 2016, 2528};
    const int Kp[3]   = {2016, 512, 416};
    int z = blockIdx.z, m = z / 3, t = z - m * 3;
    GP p;
    p.Ah = g_ah; p.Al = g_al; p.ldA = APAD; p.colA = colA[m];
    p.B  = g_wh + (size_t)t * 256 * APAD;
    p.ldB = APAD; p.colB = colA[m];
    p.Kp = Kp[m];
    p.bias = biases.b[t * 3 + m];
    p.C = ((t == 0) ? g_q : (t == 1) ? g_k : g_v) + m * 256;
    p.ldc = QKV_LD;
    gemm_body(p);
}

__global__ void __launch_bounds__(256, 2) fc_gemm_kernel(const float* fc_b)
{
    GP p;
    p.Ah = g_oh; p.Al = g_ol; p.ldA = 256; p.colA = 0;
    p.B  = g_fch; p.ldB = 256; p.colB = 0;
    p.Kp = 256;
    p.bias = fc_b; p.C = g_fc; p.ldc = 256;
    gemm_body(p);
}

// ------------- attention logits + global min ---------------------------------
__global__ void __launch_bounds__(256) attn_logits_kernel()
{
    int t  = blockIdx.x * blockDim.x + threadIdx.x;
    int bs = t >> 3, h = t & 7;
    const float4* qb = (const float4*)(g_q + bs * QKV_LD + h * 32);
    const float4* kb = (const float4*)(g_k + bs * QKV_LD + h * 32);

    float4 kr[3][8];
#pragma unroll
    for (int n = 0; n < 3; n++)
#pragma unroll
        for (int j = 0; j < 8; j++) kr[n][j] = kb[n * 64 + j];

    float lmin = 3.4e38f;
#pragma unroll
    for (int m = 0; m < 3; m++) {
        float4 qv[8];
#pragma unroll
        for (int j = 0; j < 8; j++) qv[j] = qb[m * 64 + j];
#pragma unroll
        for (int n = 0; n < 3; n++) {
            float s = 0.f;
#pragma unroll
            for (int j = 0; j < 8; j++) {
                s = fmaf(qv[j].x, kr[n][j].x, s);
                s = fmaf(qv[j].y, kr[n][j].y, s);
                s = fmaf(qv[j].z, kr[n][j].z, s);
                s = fmaf(qv[j].w, kr[n][j].w, s);
            }
            s *= TEMP_INV;
            g_logits[t * 9 + m * 3 + n] = s;
            lmin = fminf(lmin, s);
        }
    }
#pragma unroll
    for (int off = 16; off; off >>= 1)
        lmin = fminf(lmin, __shfl_xor_sync(0xFFFFFFFFu, lmin, off));
    if ((threadIdx.x & 31) == 0) atomicMin(&g_minkey, f2key(lmin));
}

// ------------- scale / L1 / softmax / PV -> fp16 hi/lo o ----------------------
__global__ void __launch_bounds__(256) attn_softmax_o_kernel()
{
    int t  = blockIdx.x * blockDim.x + threadIdx.x;
    int bs = t >> 3, h = t & 7;
    float inv = 1.0f / fabsf(key2f(g_minkey));

    const float* lg = g_logits + t * 9;
    const float4* vb = (const float4*)(g_v + bs * QKV_LD + h * 32);
    size_t obase = (size_t)bs * QKV_LD + h * 32;

#pragma unroll
    for (int m = 0; m < 3; m++) {
        float r0 = lg[m*3+0]*inv, r1 = lg[m*3+1]*inv, r2 = lg[m*3+2]*inv;
        float l1 = fmaxf(fabsf(r0) + fabsf(r1) + fabsf(r2), 1e-12f);
        r0 /= l1; r1 /= l1; r2 /= l1;
        float mx = fmaxf(r0, fmaxf(r1, r2));
        float e0 = expf(r0-mx), e1 = expf(r1-mx), e2 = expf(r2-mx);
        float es = e0 + e1 + e2;
        float p0 = e0/es, p1 = e1/es, p2 = e2/es;

        __half2* oh2 = (__half2*)&g_oh[obase + m * 256];
        __half2* ol2 = (__half2*)&g_ol[obase + m * 256];
#pragma unroll
        for (int j = 0; j < 8; j++) {
            float4 v0 = vb[j], v1 = vb[64+j], v2 = vb[128+j];
            float r[4];
            r[0] = p0*v0.x + p1*v1.x + p2*v2.x;
            r[1] = p0*v0.y + p1*v1.y + p2*v2.y;
            r[2] = p0*v0.z + p1*v1.z + p2*v2.z;
            r[3] = p0*v0.w + p1*v1.w + p2*v2.w;
            __half hh[4], ll[4];
#pragma unroll
            for (int e = 0; e < 4; e++) split_f16(r[e], hh[e], ll[e]);
            __half2 h01; h01.x = hh[0]; h01.y = hh[1];
            __half2 h23; h23.x = hh[2]; h23.y = hh[3];
            __half2 l01; l01.x = ll[0]; l01.y = ll[1];
            __half2 l23; l23.x = ll[2]; l23.y = ll[3];
            oh2[j*2]   = h01; oh2[j*2+1] = h23;
            ol2[j*2]   = l01; ol2[j*2+1] = l23;
        }
    }
}

// ------------- fused residual + layernorm + out GEMM --------------------------
__global__ void __launch_bounds__(256) ln_out_kernel(
    const float* __restrict__ ln_g, const float* __restrict__ ln_b,
    const float* __restrict__ out_w, const float* __restrict__ out_b,
    float* __restrict__ out)
{
    __shared__ float red[8][8];
    __shared__ float bcast[8];

    int s = blockIdx.x, tid = threadIdx.x;
    int lane = tid & 31, wid = tid >> 5;

    float x[3];
#pragma unroll
    for (int m = 0; m < 3; m++) {
        size_t r = (size_t)(s * 3 + m) * 256 + tid;
        x[m] = g_fc[r] + g_v[r];
    }

    float v6[6] = {x[0], x[1], x[2], x[0]*x[0], x[1]*x[1], x[2]*x[2]};
#pragma unroll
    for (int off = 16; off; off >>= 1)
#pragma unroll
        for (int i = 0; i < 6; i++)
            v6[i] += __shfl_xor_sync(0xFFFFFFFFu, v6[i], off);
    if (lane < 6) red[wid][lane] = v6[lane];
    __syncthreads();
    if (wid == 0) {
#pragma unroll
        for (int i = 0; i < 6; i++) {
            float t = (lane < 8) ? red[lane][i] : 0.f;
#pragma unroll
            for (int off = 4; off; off >>= 1)
                t += __shfl_xor_sync(0xFFFFFFFFu, t, off);
            if (lane == 0) bcast[i] = t;
        }
    }
    __syncthreads();

    float gg = ln_g[tid], bb = ln_b[tid];
    float acc[5] = {0.f, 0.f, 0.f, 0.f, 0.f};
#pragma unroll
    for (int m = 0; m < 3; m++) {
        float mu  = bcast[m] * (1.0f / 256.0f);
        float var = bcast[m + 3] * (1.0f / 256.0f) - mu * mu;
        float rstd = rsqrtf(var + LN_EPS);
        float xn = (x[m] - mu) * rstd * gg + bb;
        const float* wrow = out_w + (size_t)(m * 256 + tid) * 5;
#pragma unroll
        for (int c = 0; c < 5; c++) acc[c] = fmaf(xn, wrow[c], acc[c]);
    }
#pragma unroll
    for (int off = 16; off; off >>= 1)
#pragma unroll
        for (int c = 0; c < 5; c++)
            acc[c] += __shfl_xor_sync(0xFFFFFFFFu, acc[c], off);
    if (lane < 5) red[wid][lane] = acc[lane];
    __syncthreads();
    if (wid == 0 && lane < 5) {
        float t = 0.f;
#pragma unroll
        for (int w = 0; w < 8; w++) t += red[w][lane];
        out[s * 5 + lane] = t + out_b[lane];
    }
}

// ==============================================================================
extern "C" void kernel_launch(void* const* d_in, const int* in_sizes, int n_in,
                              void* d_out, int out_size)
{
    const float* X = (const float*)d_in[0];
    W9 ws; B9 bs;
    for (int t = 0; t < 3; t++)
        for (int m = 0; m < 3; m++) {
            ws.w[t*3+m] = (const float*)d_in[1 + t*6 + m*2];
            bs.b[t*3+m] = (const float*)d_in[2 + t*6 + m*2];
        }
    const float* fc_w  = (const float*)d_in[19];
    const float* fc_b  = (const float*)d_in[20];
    const float* ln_g  = (const float*)d_in[21];
    const float* ln_b  = (const float*)d_in[22];
    const float* out_w = (const float*)d_in[23];
    const float* out_b = (const float*)d_in[24];
    float* out = (float*)d_out;

    static int smem_set = 0;
    if (!smem_set) {
        cudaFuncSetAttribute(qkv_gemm_kernel, cudaFuncAttributeMaxDynamicSharedMemorySize, SMEM_GEMM);
        cudaFuncSetAttribute(fc_gemm_kernel,  cudaFuncAttributeMaxDynamicSharedMemorySize, SMEM_GEMM);
        smem_set = 1;
    }

    init_min_kernel<<<1, 1>>>();                    // idx 0
    conv_x_kernel<<<dim3(6, BSZ), 256>>>(X);        // idx 1
    conv_w_kernel<<<dim3(1008, 1, 9), 256>>>(ws);   // idx 2

    qkv_gemm_kernel<<<dim3(2, BSZ/128, 9), 256, SMEM_GEMM>>>(bs);  // idx 3 -> ncu target

    conv_fcw_kernel<<<128, 256>>>(fc_w);            // idx 4

    attn_logits_kernel<<<(BSZ*8)/256, 256>>>();
    attn_softmax_o_kernel<<<(BSZ*8)/256, 256>>>();

    fc_gemm_kernel<<<dim3(2, NROWS/128, 1), 256, SMEM_GEMM>>>(fc_b);

    ln_out_kernel<<<BSZ, 256>>>(ln_g, ln_b, out_w, out_b, out);
}

// round 8
// speedup vs baseline: 3.7677x; 1.2180x over previous
#include <cuda_runtime.h>
#include <cuda_fp16.h>
#include <cstdint>

#define BSZ    16384
#define QKV_LD 768
#define NROWS  (BSZ*3)
#define LN_EPS 1e-6f
#define TEMP_INV 0.17677669529663687f
#define APAD   3072      // A layout stride; used cols = 2016+512+416 = 2944

// ---------------- scratch (static device arrays; no cudaMalloc) --------------
__device__ __align__(16) float g_q [BSZ*QKV_LD];
__device__ __align__(16) float g_k [BSZ*QKV_LD];
__device__ __align__(16) float g_v [BSZ*QKV_LD];
__device__ __align__(16) float g_fc[BSZ*QKV_LD];
__device__ __align__(16) float g_logits[BSZ*8*9];
__device__ unsigned g_minkey;

__device__ __align__(16) __half g_ah[(size_t)BSZ*APAD];
__device__ __align__(16) __half g_al[(size_t)BSZ*APAD];
__device__ __align__(16) __half g_wh[(size_t)3*256*APAD];
__device__ __align__(16) __half g_oh[(size_t)NROWS*256];
__device__ __align__(16) __half g_ol[(size_t)NROWS*256];
__device__ __align__(16) __half g_fch[256*256];

// ---------------- small helpers ----------------------------------------------
__device__ __forceinline__ unsigned f2key(float f) {
    unsigned u = __float_as_uint(f);
    return (u & 0x80000000u) ? ~u : (u | 0x80000000u);
}
__device__ __forceinline__ float key2f(unsigned k) {
    unsigned u = (k & 0x80000000u) ? (k & 0x7FFFFFFFu) : ~k;
    return __uint_as_float(u);
}
__global__ void init_min_kernel() { g_minkey = 0xFFFFFFFFu; }

__device__ __forceinline__ uint32_t su32(const void* p) {
    return (uint32_t)__cvta_generic_to_shared(p);
}
__device__ __forceinline__ void cp16(uint32_t dst, const void* src) {
    asm volatile("cp.async.cg.shared.global [%0], [%1], 16;"
                 :: "r"(dst), "l"(src) : "memory");
}
__device__ __forceinline__ void cp_commit() {
    asm volatile("cp.async.commit_group;" ::: "memory");
}
__device__ __forceinline__ void ldm_x4(uint32_t& r0, uint32_t& r1, uint32_t& r2,
                                       uint32_t& r3, uint32_t addr) {
    asm volatile("ldmatrix.sync.aligned.m8n8.x4.shared.b16 {%0,%1,%2,%3}, [%4];"
                 : "=r"(r0), "=r"(r1), "=r"(r2), "=r"(r3) : "r"(addr));
}
__device__ __forceinline__ void mma_f16(float* c, uint32_t a0, uint32_t a1,
                                        uint32_t a2, uint32_t a3,
                                        uint32_t b0, uint32_t b1) {
    asm volatile(
        "mma.sync.aligned.m16n8k16.row.col.f32.f16.f16.f32 "
        "{%0,%1,%2,%3}, {%4,%5,%6,%7}, {%8,%9}, {%0,%1,%2,%3};"
        : "+f"(c[0]), "+f"(c[1]), "+f"(c[2]), "+f"(c[3])
        : "r"(a0), "r"(a1), "r"(a2), "r"(a3), "r"(b0), "r"(b1));
}
__device__ __forceinline__ void split_f16(float v, __half& h, __half& l) {
    h = __float2half(v);
    l = __float2half(v - __half2float(h));
}

// ---------------- conversion kernels -----------------------------------------
// padded segments: [0,2016) <- X[0,2000); [2016,2528) <- X[2000,2500); [2528,2944) <- X[2500,2900)
__global__ void __launch_bounds__(256) conv_x_kernel(const float* __restrict__ X)
{
    int col2 = (blockIdx.x * 256 + threadIdx.x) * 2;
    int row  = blockIdx.y;
    __half h[2], l[2];
#pragma unroll
    for (int e = 0; e < 2; e++) {
        int col = col2 + e;
        float x = 0.f;
        if (col < 2016)      { if (col < 2000) x = X[(size_t)row*2900 + col]; }
        else if (col < 2528) { int c = col-2016; if (c < 500) x = X[(size_t)row*2900 + 2000 + c]; }
        else                 { int c = col-2528; if (c < 400) x = X[(size_t)row*2900 + 2500 + c]; }
        split_f16(x, h[e], l[e]);
    }
    __half2 hh; hh.x = h[0]; hh.y = h[1];
    __half2 ll; ll.x = l[0]; ll.y = l[1];
    *(__half2*)&g_ah[(size_t)row*APAD + col2] = hh;
    *(__half2*)&g_al[(size_t)row*APAD + col2] = ll;
}

struct W9 { const float* w[9]; };
__global__ void __launch_bounds__(256) conv_w_kernel(W9 ws)
{
    const int Km[3]   = {2000, 500, 400};
    const int Kp[3]   = {2016, 512, 416};
    const int colA[3] = {0, 2016, 2528};
    int z = blockIdx.z, t = z / 3, m = z - t * 3;
    int idx = (blockIdx.x * 256 + threadIdx.x) * 2;
    if (idx >= 256 * Kp[m]) return;
    int n  = idx / Kp[m];
    int kp = idx - n * Kp[m];
    const float* W = ws.w[z];
    float x0 = (kp     < Km[m]) ? W[(size_t)kp*256 + n]     : 0.f;
    float x1 = (kp + 1 < Km[m]) ? W[(size_t)(kp+1)*256 + n] : 0.f;
    __half2 hh; hh.x = __float2half(x0); hh.y = __float2half(x1);
    size_t o = (size_t)t*256*APAD + (size_t)n*APAD + colA[m] + kp;
    *(__half2*)&g_wh[o] = hh;
}

__global__ void __launch_bounds__(256) conv_fcw_kernel(const float* __restrict__ fcw)
{
    int idx = (blockIdx.x * 256 + threadIdx.x) * 2;
    int n = idx >> 8, k = idx & 255;
    __half2 hh;
    hh.x = __float2half(fcw[(size_t)k*256 + n]);
    hh.y = __float2half(fcw[(size_t)(k+1)*256 + n]);
    *(__half2*)&g_fch[n*256 + k] = hh;
}

// ---------------- mma.sync split-fp16 GEMM -------------------------------------
// C[M,256] = A[M,K] @ B[256,K]-rows + bias
// nprod=2: pass1 Ah, pass2 Al (full split);  nprod=1: Ah only (logits path)
struct GP {
    const __half *Ah, *Al, *B;
    int ldA, ldB, colA, colB, Kp, nprod;
    const float* bias;
    float* C; int ldc;
};

// stage: A 128x80B + B 128x80B  (K-chunk 32, 80B padded rows); 5 stages
#define SOFF_B 10240
#define SSTG   20480
#define NSTAGE 5
#define SMEM_GEMM (NSTAGE*SSTG)   // 102400 -> 2 CTAs/SM (200KB)

__device__ __forceinline__ void gemm_body(const GP p)
{
    extern __shared__ __align__(16) char dsm[];
    const int tid  = threadIdx.x;
    const int lane = tid & 31, wid = tid >> 5;
    const int wm = wid >> 2, wn = wid & 3;            // 2x4 warp grid
    const int row0 = blockIdx.y * 128, col0 = blockIdx.x * 128;
    const uint32_t sbase = su32(dsm);

    const int ck = p.Kp >> 5;          // K=32 chunks per segment
    const int nchunk = p.nprod * ck;

    auto load_chunk = [&](int c, int buf) {
        int seg = (c >= ck);
        int kc  = seg ? c - ck : c;
        const __half* A  = seg ? p.Al : p.Ah;
        const __half* As = A + (size_t)row0 * p.ldA + p.colA + kc * 32;
        const __half* Bs = p.B + (size_t)col0 * p.ldB + p.colB + kc * 32;
        uint32_t Sd = sbase + buf * SSTG;
#pragma unroll
        for (int i = 0; i < 2; i++) {
            int id = i * 256 + tid, r = id >> 2, kg = id & 3;
            cp16(Sd + r * 80 + kg * 16, As + (size_t)r * p.ldA + kg * 8);
            cp16(Sd + SOFF_B + r * 80 + kg * 16, Bs + (size_t)r * p.ldB + kg * 8);
        }
    };

    float acc[4][4][4];
#pragma unroll
    for (int i = 0; i < 4; i++)
#pragma unroll
        for (int j = 0; j < 4; j++)
#pragma unroll
            for (int r = 0; r < 4; r++) acc[i][j][r] = 0.f;

    // preload chunks 0..2 into buffers 0..2 (3 commit groups); nchunk >= 8 always
    load_chunk(0, 0); cp_commit();
    load_chunk(1, 1); cp_commit();
    load_chunk(2, 2); cp_commit();

    // per-lane ldmatrix byte offsets (80B smem row stride)
    const uint32_t a_off = (uint32_t)((wm * 64 + (lane & 15)) * 80 + ((lane >> 4) << 4));
    const uint32_t b_off = (uint32_t)((wn * 32 + (lane & 7) + ((lane & 16) >> 1)) * 80
                                      + ((lane & 8) << 1));

    int bufc = 0;                       // buffer holding chunk c
    for (int c = 0; c < nchunk; c++) {
        // issue chunk c+3 into buffer (c+3)%5 == (c-2)%5; its readers (chunk c-2)
        // are fenced by the previous iteration's __syncthreads -> WAR-safe.
        int bnew = bufc + 3; if (bnew >= NSTAGE) bnew -= NSTAGE;
        if (c + 3 < nchunk) load_chunk(c + 3, bnew);
        cp_commit();
        asm volatile("cp.async.wait_group 3;" ::: "memory");  // chunk c resident
        __syncthreads();

        const uint32_t Sd = sbase + bufc * SSTG;
        const uint32_t Ab = Sd + a_off;
        const uint32_t Bb = Sd + SOFF_B + b_off;
#pragma unroll
        for (int kstep = 0; kstep < 2; kstep++) {
            const uint32_t kk = kstep * 32;
            uint32_t a[4][4], b[2][4];
#pragma unroll
            for (int mt = 0; mt < 4; mt++)
                ldm_x4(a[mt][0], a[mt][1], a[mt][2], a[mt][3],
                       Ab + mt * (16 * 80) + kk);
#pragma unroll
            for (int ng = 0; ng < 2; ng++)
                ldm_x4(b[ng][0], b[ng][1], b[ng][2], b[ng][3],
                       Bb + ng * (16 * 80) + kk);
#pragma unroll
            for (int mt = 0; mt < 4; mt++)
#pragma unroll
                for (int nt = 0; nt < 4; nt++)
                    mma_f16(acc[mt][nt],
                            a[mt][0], a[mt][1], a[mt][2], a[mt][3],
                            b[nt >> 1][(nt & 1) * 2], b[nt >> 1][(nt & 1) * 2 + 1]);
        }
        bufc++; if (bufc == NSTAGE) bufc = 0;
    }

    // epilogue
    const int grp = lane >> 2, tig = lane & 3;
#pragma unroll
    for (int mt = 0; mt < 4; mt++) {
        int r = row0 + wm * 64 + mt * 16 + grp;
#pragma unroll
        for (int nt = 0; nt < 4; nt++) {
            int col = col0 + wn * 32 + nt * 8 + tig * 2;
            float b0 = p.bias[col], b1 = p.bias[col + 1];
            float2 lo, hi;
            lo.x = acc[mt][nt][0] + b0; lo.y = acc[mt][nt][1] + b1;
            hi.x = acc[mt][nt][2] + b0; hi.y = acc[mt][nt][3] + b1;
            *(float2*)(p.C + (size_t)r * p.ldc + col) = lo;
            *(float2*)(p.C + (size_t)(r + 8) * p.ldc + col) = hi;
        }
    }
}

struct B9 { const float* b[9]; };

// z = m*3 + t  (q/k/v of same modality adjacent: A stays L2-hot)
// Q,K: single product (logits are L1-normalized + softmaxed -> tolerant)
// V: full 2-product split (direct linear path to output)
__global__ void __launch_bounds__(256, 2) qkv_gemm_kernel(B9 biases)
{
    const int colA[3] = {0, 2016, 2528};
    const int Kp[3]   = {2016, 512, 416};
    int z = blockIdx.z, m = z / 3, t = z - m * 3;
    GP p;
    p.Ah = g_ah; p.Al = g_al; p.ldA = APAD; p.colA = colA[m];
    p.B  = g_wh + (size_t)t * 256 * APAD;
    p.ldB = APAD; p.colB = colA[m];
    p.Kp = Kp[m];
    p.nprod = (t == 2) ? 2 : 1;
    p.bias = biases.b[t * 3 + m];
    p.C = ((t == 0) ? g_q : (t == 1) ? g_k : g_v) + m * 256;
    p.ldc = QKV_LD;
    gemm_body(p);
}

__global__ void __launch_bounds__(256, 2) fc_gemm_kernel(const float* fc_b)
{
    GP p;
    p.Ah = g_oh; p.Al = g_ol; p.ldA = 256; p.colA = 0;
    p.B  = g_fch; p.ldB = 256; p.colB = 0;
    p.Kp = 256; p.nprod = 2;
    p.bias = fc_b; p.C = g_fc; p.ldc = 256;
    gemm_body(p);
}

// ------------- attention logits + global min ---------------------------------
__global__ void __launch_bounds__(256) attn_logits_kernel()
{
    int t  = blockIdx.x * blockDim.x + threadIdx.x;
    int bs = t >> 3, h = t & 7;
    const float4* qb = (const float4*)(g_q + bs * QKV_LD + h * 32);
    const float4* kb = (const float4*)(g_k + bs * QKV_LD + h * 32);

    float4 kr[3][8];
#pragma unroll
    for (int n = 0; n < 3; n++)
#pragma unroll
        for (int j = 0; j < 8; j++) kr[n][j] = kb[n * 64 + j];

    float lmin = 3.4e38f;
#pragma unroll
    for (int m = 0; m < 3; m++) {
        float4 qv[8];
#pragma unroll
        for (int j = 0; j < 8; j++) qv[j] = qb[m * 64 + j];
#pragma unroll
        for (int n = 0; n < 3; n++) {
            float s = 0.f;
#pragma unroll
            for (int j = 0; j < 8; j++) {
                s = fmaf(qv[j].x, kr[n][j].x, s);
                s = fmaf(qv[j].y, kr[n][j].y, s);
                s = fmaf(qv[j].z, kr[n][j].z, s);
                s = fmaf(qv[j].w, kr[n][j].w, s);
            }
            s *= TEMP_INV;
            g_logits[t * 9 + m * 3 + n] = s;
            lmin = fminf(lmin, s);
        }
    }
#pragma unroll
    for (int off = 16; off; off >>= 1)
        lmin = fminf(lmin, __shfl_xor_sync(0xFFFFFFFFu, lmin, off));
    if ((threadIdx.x & 31) == 0) atomicMin(&g_minkey, f2key(lmin));
}

// ------------- scale / L1 / softmax / PV -> fp16 hi/lo o ----------------------
__global__ void __launch_bounds__(256) attn_softmax_o_kernel()
{
    int t  = blockIdx.x * blockDim.x + threadIdx.x;
    int bs = t >> 3, h = t & 7;
    float inv = 1.0f / fabsf(key2f(g_minkey));

    const float* lg = g_logits + t * 9;
    const float4* vb = (const float4*)(g_v + bs * QKV_LD + h * 32);
    size_t obase = (size_t)bs * QKV_LD + h * 32;

#pragma unroll
    for (int m = 0; m < 3; m++) {
        float r0 = lg[m*3+0]*inv, r1 = lg[m*3+1]*inv, r2 = lg[m*3+2]*inv;
        float l1 = fmaxf(fabsf(r0) + fabsf(r1) + fabsf(r2), 1e-12f);
        r0 /= l1; r1 /= l1; r2 /= l1;
        float mx = fmaxf(r0, fmaxf(r1, r2));
        float e0 = expf(r0-mx), e1 = expf(r1-mx), e2 = expf(r2-mx);
        float es = e0 + e1 + e2;
        float p0 = e0/es, p1 = e1/es, p2 = e2/es;

        __half2* oh2 = (__half2*)&g_oh[obase + m * 256];
        __half2* ol2 = (__half2*)&g_ol[obase + m * 256];
#pragma unroll
        for (int j = 0; j < 8; j++) {
            float4 v0 = vb[j], v1 = vb[64+j], v2 = vb[128+j];
            float r[4];
            r[0] = p0*v0.x + p1*v1.x + p2*v2.x;
            r[1] = p0*v0.y + p1*v1.y + p2*v2.y;
            r[2] = p0*v0.z + p1*v1.z + p2*v2.z;
            r[3] = p0*v0.w + p1*v1.w + p2*v2.w;
            __half hh[4], ll[4];
#pragma unroll
            for (int e = 0; e < 4; e++) split_f16(r[e], hh[e], ll[e]);
            __half2 h01; h01.x = hh[0]; h01.y = hh[1];
            __half2 h23; h23.x = hh[2]; h23.y = hh[3];
            __half2 l01; l01.x = ll[0]; l01.y = ll[1];
            __half2 l23; l23.x = ll[2]; l23.y = ll[3];
            oh2[j*2]   = h01; oh2[j*2+1] = h23;
            ol2[j*2]   = l01; ol2[j*2+1] = l23;
        }
    }
}

// ------------- fused residual + layernorm + out GEMM --------------------------
__global__ void __launch_bounds__(256) ln_out_kernel(
    const float* __restrict__ ln_g, const float* __restrict__ ln_b,
    const float* __restrict__ out_w, const float* __restrict__ out_b,
    float* __restrict__ out)
{
    __shared__ float red[8][8];
    __shared__ float bcast[8];

    int s = blockIdx.x, tid = threadIdx.x;
    int lane = tid & 31, wid = tid >> 5;

    float x[3];
#pragma unroll
    for (int m = 0; m < 3; m++) {
        size_t r = (size_t)(s * 3 + m) * 256 + tid;
        x[m] = g_fc[r] + g_v[r];
    }

    float v6[6] = {x[0], x[1], x[2], x[0]*x[0], x[1]*x[1], x[2]*x[2]};
#pragma unroll
    for (int off = 16; off; off >>= 1)
#pragma unroll
        for (int i = 0; i < 6; i++)
            v6[i] += __shfl_xor_sync(0xFFFFFFFFu, v6[i], off);
    if (lane < 6) red[wid][lane] = v6[lane];
    __syncthreads();
    if (wid == 0) {
#pragma unroll
        for (int i = 0; i < 6; i++) {
            float t = (lane < 8) ? red[lane][i] : 0.f;
#pragma unroll
            for (int off = 4; off; off >>= 1)
                t += __shfl_xor_sync(0xFFFFFFFFu, t, off);
            if (lane == 0) bcast[i] = t;
        }
    }
    __syncthreads();

    float gg = ln_g[tid], bb = ln_b[tid];
    float acc[5] = {0.f, 0.f, 0.f, 0.f, 0.f};
#pragma unroll
    for (int m = 0; m < 3; m++) {
        float mu  = bcast[m] * (1.0f / 256.0f);
        float var = bcast[m + 3] * (1.0f / 256.0f) - mu * mu;
        float rstd = rsqrtf(var + LN_EPS);
        float xn = (x[m] - mu) * rstd * gg + bb;
        const float* wrow = out_w + (size_t)(m * 256 + tid) * 5;
#pragma unroll
        for (int c = 0; c < 5; c++) acc[c] = fmaf(xn, wrow[c], acc[c]);
    }
#pragma unroll
    for (int off = 16; off; off >>= 1)
#pragma unroll
        for (int c = 0; c < 5; c++)
            acc[c] += __shfl_xor_sync(0xFFFFFFFFu, acc[c], off);
    if (lane < 5) red[wid][lane] = acc[lane];
    __syncthreads();
    if (wid == 0 && lane < 5) {
        float t = 0.f;
#pragma unroll
        for (int w = 0; w < 8; w++) t += red[w][lane];
        out[s * 5 + lane] = t + out_b[lane];
    }
}

// ==============================================================================
extern "C" void kernel_launch(void* const* d_in, const int* in_sizes, int n_in,
                              void* d_out, int out_size)
{
    const float* X = (const float*)d_in[0];
    W9 ws; B9 bs;
    for (int t = 0; t < 3; t++)
        for (int m = 0; m < 3; m++) {
            ws.w[t*3+m] = (const float*)d_in[1 + t*6 + m*2];
            bs.b[t*3+m] = (const float*)d_in[2 + t*6 + m*2];
        }
    const float* fc_w  = (const float*)d_in[19];
    const float* fc_b  = (const float*)d_in[20];
    const float* ln_g  = (const float*)d_in[21];
    const float* ln_b  = (const float*)d_in[22];
    const float* out_w = (const float*)d_in[23];
    const float* out_b = (const float*)d_in[24];
    float* out = (float*)d_out;

    static int smem_set = 0;
    if (!smem_set) {
        cudaFuncSetAttribute(qkv_gemm_kernel, cudaFuncAttributeMaxDynamicSharedMemorySize, SMEM_GEMM);
        cudaFuncSetAttribute(fc_gemm_kernel,  cudaFuncAttributeMaxDynamicSharedMemorySize, SMEM_GEMM);
        smem_set = 1;
    }

    init_min_kernel<<<1, 1>>>();                    // idx 0
    conv_x_kernel<<<dim3(6, BSZ), 256>>>(X);        // idx 1
    conv_w_kernel<<<dim3(1008, 1, 9), 256>>>(ws);   // idx 2

    qkv_gemm_kernel<<<dim3(2, BSZ/128, 9), 256, SMEM_GEMM>>>(bs);  // idx 3 -> ncu target

    conv_fcw_kernel<<<128, 256>>>(fc_w);            // idx 4

    attn_logits_kernel<<<(BSZ*8)/256, 256>>>();
    attn_softmax_o_kernel<<<(BSZ*8)/256, 256>>>();

    fc_gemm_kernel<<<dim3(2, NROWS/128, 1), 256, SMEM_GEMM>>>(fc_b);

    ln_out_kernel<<<BSZ, 256>>>(ln_g, ln_b, out_w, out_b, out);
}

// round 9
// speedup vs baseline: 4.0149x; 1.0656x over previous
#include <cuda_runtime.h>
#include <cuda_fp16.h>
#include <cstdint>

#define BSZ    16384
#define QKV_LD 768
#define NROWS  (BSZ*3)
#define LN_EPS 1e-6f
#define TEMP_INV 0.17677669529663687f
#define APAD   3072      // A layout stride; used cols = 2048+512+448 = 3008

// ---------------- scratch (static device arrays; no cudaMalloc) --------------
__device__ __align__(16) float g_q [BSZ*QKV_LD];
__device__ __align__(16) float g_k [BSZ*QKV_LD];
__device__ __align__(16) float g_v [BSZ*QKV_LD];
__device__ __align__(16) float g_fc[BSZ*QKV_LD];
__device__ __align__(16) float g_logits[BSZ*8*9];
__device__ unsigned g_minkey;

__device__ __align__(16) __half g_ah[(size_t)BSZ*APAD];
__device__ __align__(16) __half g_al[(size_t)BSZ*APAD];
__device__ __align__(16) __half g_wh[(size_t)3*256*APAD];
__device__ __align__(16) __half g_oh[(size_t)NROWS*256];
__device__ __align__(16) __half g_ol[(size_t)NROWS*256];
__device__ __align__(16) __half g_fch[256*256];

// ---------------- small helpers ----------------------------------------------
__device__ __forceinline__ unsigned f2key(float f) {
    unsigned u = __float_as_uint(f);
    return (u & 0x80000000u) ? ~u : (u | 0x80000000u);
}
__device__ __forceinline__ float key2f(unsigned k) {
    unsigned u = (k & 0x80000000u) ? (k & 0x7FFFFFFFu) : ~k;
    return __uint_as_float(u);
}
__global__ void init_min_kernel() { g_minkey = 0xFFFFFFFFu; }

__device__ __forceinline__ uint32_t su32(const void* p) {
    return (uint32_t)__cvta_generic_to_shared(p);
}
__device__ __forceinline__ void cp16(uint32_t dst, const void* src) {
    asm volatile("cp.async.cg.shared.global [%0], [%1], 16;"
                 :: "r"(dst), "l"(src) : "memory");
}
__device__ __forceinline__ void cp_commit() {
    asm volatile("cp.async.commit_group;" ::: "memory");
}
__device__ __forceinline__ void ldm_x4(uint32_t& r0, uint32_t& r1, uint32_t& r2,
                                       uint32_t& r3, uint32_t addr) {
    asm volatile("ldmatrix.sync.aligned.m8n8.x4.shared.b16 {%0,%1,%2,%3}, [%4];"
                 : "=r"(r0), "=r"(r1), "=r"(r2), "=r"(r3) : "r"(addr));
}
__device__ __forceinline__ void mma_f16(float* c, uint32_t a0, uint32_t a1,
                                        uint32_t a2, uint32_t a3,
                                        uint32_t b0, uint32_t b1) {
    asm volatile(
        "mma.sync.aligned.m16n8k16.row.col.f32.f16.f16.f32 "
        "{%0,%1,%2,%3}, {%4,%5,%6,%7}, {%8,%9}, {%0,%1,%2,%3};"
        : "+f"(c[0]), "+f"(c[1]), "+f"(c[2]), "+f"(c[3])
        : "r"(a0), "r"(a1), "r"(a2), "r"(a3), "r"(b0), "r"(b1));
}
__device__ __forceinline__ void split_f16(float v, __half& h, __half& l) {
    h = __float2half(v);
    l = __float2half(v - __half2float(h));
}

// ---------------- conversion kernels -----------------------------------------
// padded segments: [0,2048) <- X[0,2000); [2048,2560) <- X[2000,2500); [2560,3008) <- X[2500,2900)
__global__ void __launch_bounds__(256) conv_x_kernel(const float* __restrict__ X)
{
    int col2 = (blockIdx.x * 256 + threadIdx.x) * 2;
    int row  = blockIdx.y;
    __half h[2], l[2];
#pragma unroll
    for (int e = 0; e < 2; e++) {
        int col = col2 + e;
        float x = 0.f;
        if (col < 2048)      { if (col < 2000) x = X[(size_t)row*2900 + col]; }
        else if (col < 2560) { int c = col-2048; if (c < 500) x = X[(size_t)row*2900 + 2000 + c]; }
        else                 { int c = col-2560; if (c < 400) x = X[(size_t)row*2900 + 2500 + c]; }
        split_f16(x, h[e], l[e]);
    }
    __half2 hh; hh.x = h[0]; hh.y = h[1];
    __half2 ll; ll.x = l[0]; ll.y = l[1];
    *(__half2*)&g_ah[(size_t)row*APAD + col2] = hh;
    *(__half2*)&g_al[(size_t)row*APAD + col2] = ll;
}

struct W9 { const float* w[9]; };
__global__ void __launch_bounds__(256) conv_w_kernel(W9 ws)
{
    const int Km[3]   = {2000, 500, 400};
    const int Kp[3]   = {2048, 512, 448};
    const int colA[3] = {0, 2048, 2560};
    int z = blockIdx.z, t = z / 3, m = z - t * 3;
    int idx = (blockIdx.x * 256 + threadIdx.x) * 2;
    if (idx >= 256 * Kp[m]) return;
    int n  = idx / Kp[m];
    int kp = idx - n * Kp[m];
    const float* W = ws.w[z];
    float x0 = (kp     < Km[m]) ? W[(size_t)kp*256 + n]     : 0.f;
    float x1 = (kp + 1 < Km[m]) ? W[(size_t)(kp+1)*256 + n] : 0.f;
    __half2 hh; hh.x = __float2half(x0); hh.y = __float2half(x1);
    size_t o = (size_t)t*256*APAD + (size_t)n*APAD + colA[m] + kp;
    *(__half2*)&g_wh[o] = hh;
}

__global__ void __launch_bounds__(256) conv_fcw_kernel(const float* __restrict__ fcw)
{
    int idx = (blockIdx.x * 256 + threadIdx.x) * 2;
    int n = idx >> 8, k = idx & 255;
    __half2 hh;
    hh.x = __float2half(fcw[(size_t)k*256 + n]);
    hh.y = __float2half(fcw[(size_t)(k+1)*256 + n]);
    *(__half2*)&g_fch[n*256 + k] = hh;
}

// ---------------- mma.sync split-fp16 GEMM -------------------------------------
// C[M,256] = A[M,K] @ B[256,K]-rows + bias
// nprod=2: pass1 Ah, pass2 Al (full split);  nprod=1: Ah only (logits path)
struct GP {
    const __half *Ah, *Al, *B;
    int ldA, ldB, colA, colB, Kp, nprod;
    const float* bias;
    float* C; int ldc;
};

// stage: A 128x144B + B 128x144B  (K-chunk 64, 144B padded rows); 3 stages
#define SOFF_B 18432
#define SSTG   36864
#define NSTAGE 3
#define SMEM_GEMM (NSTAGE*SSTG)   // 110592 -> 2 CTAs/SM (216KB)

__device__ __forceinline__ void gemm_body(const GP p)
{
    extern __shared__ __align__(16) char dsm[];
    const int tid  = threadIdx.x;
    const int lane = tid & 31, wid = tid >> 5;
    const int wm = wid >> 2, wn = wid & 3;            // 2x4 warp grid
    const int row0 = blockIdx.y * 128, col0 = blockIdx.x * 128;
    const uint32_t sbase = su32(dsm);

    const int ck = p.Kp >> 6;          // K=64 chunks per segment
    const int nchunk = p.nprod * ck;

    auto load_chunk = [&](int c, int buf) {
        int seg = (c >= ck);
        int kc  = seg ? c - ck : c;
        const __half* A  = seg ? p.Al : p.Ah;
        const __half* As = A + (size_t)row0 * p.ldA + p.colA + kc * 64;
        const __half* Bs = p.B + (size_t)col0 * p.ldB + p.colB + kc * 64;
        uint32_t Sd = sbase + buf * SSTG;
#pragma unroll
        for (int i = 0; i < 4; i++) {
            int id = i * 256 + tid, r = id >> 3, kg = id & 7;
            cp16(Sd + r * 144 + kg * 16, As + (size_t)r * p.ldA + kg * 8);
            cp16(Sd + SOFF_B + r * 144 + kg * 16, Bs + (size_t)r * p.ldB + kg * 8);
        }
    };

    float acc[4][4][4];
#pragma unroll
    for (int i = 0; i < 4; i++)
#pragma unroll
        for (int j = 0; j < 4; j++)
#pragma unroll
            for (int r = 0; r < 4; r++) acc[i][j][r] = 0.f;

    load_chunk(0, 0); cp_commit();

    // per-lane ldmatrix byte offsets (144B smem row stride)
    const uint32_t a_off = (uint32_t)((wm * 64 + (lane & 15)) * 144 + ((lane >> 4) << 4));
    const uint32_t b_off = (uint32_t)((wn * 32 + (lane & 7) + ((lane & 16) >> 1)) * 144
                                      + ((lane & 8) << 1));

    int bufc = 0;                       // buffer holding chunk c
    for (int c = 0; c < nchunk; c++) {
        // issue chunk c+1 into buffer (c+1)%3; its previous readers were chunk
        // c-2, fenced by iteration c-1's __syncthreads -> WAR-safe.
        int bnew = bufc + 1; if (bnew == NSTAGE) bnew = 0;
        if (c + 1 < nchunk) {
            load_chunk(c + 1, bnew); cp_commit();
            asm volatile("cp.async.wait_group 1;" ::: "memory");
        } else {
            asm volatile("cp.async.wait_group 0;" ::: "memory");
        }
        __syncthreads();

        const uint32_t Sd = sbase + bufc * SSTG;
        const uint32_t Ab = Sd + a_off;
        const uint32_t Bb = Sd + SOFF_B + b_off;
#pragma unroll
        for (int kstep = 0; kstep < 4; kstep++) {
            const uint32_t kk = kstep * 32;
            uint32_t a[4][4], b[2][4];
#pragma unroll
            for (int mt = 0; mt < 4; mt++)
                ldm_x4(a[mt][0], a[mt][1], a[mt][2], a[mt][3],
                       Ab + mt * (16 * 144) + kk);
#pragma unroll
            for (int ng = 0; ng < 2; ng++)
                ldm_x4(b[ng][0], b[ng][1], b[ng][2], b[ng][3],
                       Bb + ng * (16 * 144) + kk);
#pragma unroll
            for (int mt = 0; mt < 4; mt++)
#pragma unroll
                for (int nt = 0; nt < 4; nt++)
                    mma_f16(acc[mt][nt],
                            a[mt][0], a[mt][1], a[mt][2], a[mt][3],
                            b[nt >> 1][(nt & 1) * 2], b[nt >> 1][(nt & 1) * 2 + 1]);
        }
        bufc = bnew;
    }

    // epilogue
    const int grp = lane >> 2, tig = lane & 3;
#pragma unroll
    for (int mt = 0; mt < 4; mt++) {
        int r = row0 + wm * 64 + mt * 16 + grp;
#pragma unroll
        for (int nt = 0; nt < 4; nt++) {
            int col = col0 + wn * 32 + nt * 8 + tig * 2;
            float b0 = p.bias[col], b1 = p.bias[col + 1];
            float2 lo, hi;
            lo.x = acc[mt][nt][0] + b0; lo.y = acc[mt][nt][1] + b1;
            hi.x = acc[mt][nt][2] + b0; hi.y = acc[mt][nt][3] + b1;
            *(float2*)(p.C + (size_t)r * p.ldc + col) = lo;
            *(float2*)(p.C + (size_t)(r + 8) * p.ldc + col) = hi;
        }
    }
}

struct B9 { const float* b[9]; };

// z = m*3 + t  (q/k/v of same modality adjacent: A stays L2-hot)
// Q,K: single product (logits are L1-normalized + softmaxed -> tolerant)
// V: full 2-product split (direct linear path to output)
__global__ void __launch_bounds__(256, 2) qkv_gemm_kernel(B9 biases)
{
    const int colA[3] = {0, 2048, 2560};
    const int Kp[3]   = {2048, 512, 448};
    int z = blockIdx.z, m = z / 3, t = z - m * 3;
    GP p;
    p.Ah = g_ah; p.Al = g_al; p.ldA = APAD; p.colA = colA[m];
    p.B  = g_wh + (size_t)t * 256 * APAD;
    p.ldB = APAD; p.colB = colA[m];
    p.Kp = Kp[m];
    p.nprod = (t == 2) ? 2 : 1;
    p.bias = biases.b[t * 3 + m];
    p.C = ((t == 0) ? g_q : (t == 1) ? g_k : g_v) + m * 256;
    p.ldc = QKV_LD;
    gemm_body(p);
}

__global__ void __launch_bounds__(256, 2) fc_gemm_kernel(const float* fc_b)
{
    GP p;
    p.Ah = g_oh; p.Al = g_ol; p.ldA = 256; p.colA = 0;
    p.B  = g_fch; p.ldB = 256; p.colB = 0;
    p.Kp = 256; p.nprod = 2;
    p.bias = fc_b; p.C = g_fc; p.ldc = 256;
    gemm_body(p);
}

// ------------- attention logits + global min ---------------------------------
__global__ void __launch_bounds__(256) attn_logits_kernel()
{
    int t  = blockIdx.x * blockDim.x + threadIdx.x;
    int bs = t >> 3, h = t & 7;
    const float4* qb = (const float4*)(g_q + bs * QKV_LD + h * 32);
    const float4* kb = (const float4*)(g_k + bs * QKV_LD + h * 32);

    float4 kr[3][8];
#pragma unroll
    for (int n = 0; n < 3; n++)
#pragma unroll
        for (int j = 0; j < 8; j++) kr[n][j] = kb[n * 64 + j];

    float lmin = 3.4e38f;
#pragma unroll
    for (int m = 0; m < 3; m++) {
        float4 qv[8];
#pragma unroll
        for (int j = 0; j < 8; j++) qv[j] = qb[m * 64 + j];
#pragma unroll
        for (int n = 0; n < 3; n++) {
            float s = 0.f;
#pragma unroll
            for (int j = 0; j < 8; j++) {
                s = fmaf(qv[j].x, kr[n][j].x, s);
                s = fmaf(qv[j].y, kr[n][j].y, s);
                s = fmaf(qv[j].z, kr[n][j].z, s);
                s = fmaf(qv[j].w, kr[n][j].w, s);
            }
            s *= TEMP_INV;
            g_logits[t * 9 + m * 3 + n] = s;
            lmin = fminf(lmin, s);
        }
    }
#pragma unroll
    for (int off = 16; off; off >>= 1)
        lmin = fminf(lmin, __shfl_xor_sync(0xFFFFFFFFu, lmin, off));
    if ((threadIdx.x & 31) == 0) atomicMin(&g_minkey, f2key(lmin));
}

// ------------- scale / L1 / softmax / PV -> fp16 hi/lo o ----------------------
__global__ void __launch_bounds__(256) attn_softmax_o_kernel()
{
    int t  = blockIdx.x * blockDim.x + threadIdx.x;
    int bs = t >> 3, h = t & 7;
    float inv = 1.0f / fabsf(key2f(g_minkey));

    const float* lg = g_logits + t * 9;
    const float4* vb = (const float4*)(g_v + bs * QKV_LD + h * 32);
    size_t obase = (size_t)bs * QKV_LD + h * 32;

#pragma unroll
    for (int m = 0; m < 3; m++) {
        float r0 = lg[m*3+0]*inv, r1 = lg[m*3+1]*inv, r2 = lg[m*3+2]*inv;
        float l1 = fmaxf(fabsf(r0) + fabsf(r1) + fabsf(r2), 1e-12f);
        r0 /= l1; r1 /= l1; r2 /= l1;
        float mx = fmaxf(r0, fmaxf(r1, r2));
        float e0 = expf(r0-mx), e1 = expf(r1-mx), e2 = expf(r2-mx);
        float es = e0 + e1 + e2;
        float p0 = e0/es, p1 = e1/es, p2 = e2/es;

        __half2* oh2 = (__half2*)&g_oh[obase + m * 256];
        __half2* ol2 = (__half2*)&g_ol[obase + m * 256];
#pragma unroll
        for (int j = 0; j < 8; j++) {
            float4 v0 = vb[j], v1 = vb[64+j], v2 = vb[128+j];
            float r[4];
            r[0] = p0*v0.x + p1*v1.x + p2*v2.x;
            r[1] = p0*v0.y + p1*v1.y + p2*v2.y;
            r[2] = p0*v0.z + p1*v1.z + p2*v2.z;
            r[3] = p0*v0.w + p1*v1.w + p2*v2.w;
            __half hh[4], ll[4];
#pragma unroll
            for (int e = 0; e < 4; e++) split_f16(r[e], hh[e], ll[e]);
            __half2 h01; h01.x = hh[0]; h01.y = hh[1];
            __half2 h23; h23.x = hh[2]; h23.y = hh[3];
            __half2 l01; l01.x = ll[0]; l01.y = ll[1];
            __half2 l23; l23.x = ll[2]; l23.y = ll[3];
            oh2[j*2]   = h01; oh2[j*2+1] = h23;
            ol2[j*2]   = l01; ol2[j*2+1] = l23;
        }
    }
}

// ------------- fused residual + layernorm + out GEMM --------------------------
__global__ void __launch_bounds__(256) ln_out_kernel(
    const float* __restrict__ ln_g, const float* __restrict__ ln_b,
    const float* __restrict__ out_w, const float* __restrict__ out_b,
    float* __restrict__ out)
{
    __shared__ float red[8][8];
    __shared__ float bcast[8];

    int s = blockIdx.x, tid = threadIdx.x;
    int lane = tid & 31, wid = tid >> 5;

    float x[3];
#pragma unroll
    for (int m = 0; m < 3; m++) {
        size_t r = (size_t)(s * 3 + m) * 256 + tid;
        x[m] = g_fc[r] + g_v[r];
    }

    float v6[6] = {x[0], x[1], x[2], x[0]*x[0], x[1]*x[1], x[2]*x[2]};
#pragma unroll
    for (int off = 16; off; off >>= 1)
#pragma unroll
        for (int i = 0; i < 6; i++)
            v6[i] += __shfl_xor_sync(0xFFFFFFFFu, v6[i], off);
    if (lane < 6) red[wid][lane] = v6[lane];
    __syncthreads();
    if (wid == 0) {
#pragma unroll
        for (int i = 0; i < 6; i++) {
            float t = (lane < 8) ? red[lane][i] : 0.f;
#pragma unroll
            for (int off = 4; off; off >>= 1)
                t += __shfl_xor_sync(0xFFFFFFFFu, t, off);
            if (lane == 0) bcast[i] = t;
        }
    }
    __syncthreads();

    float gg = ln_g[tid], bb = ln_b[tid];
    float acc[5] = {0.f, 0.f, 0.f, 0.f, 0.f};
#pragma unroll
    for (int m = 0; m < 3; m++) {
        float mu  = bcast[m] * (1.0f / 256.0f);
        float var = bcast[m + 3] * (1.0f / 256.0f) - mu * mu;
        float rstd = rsqrtf(var + LN_EPS);
        float xn = (x[m] - mu) * rstd * gg + bb;
        const float* wrow = out_w + (size_t)(m * 256 + tid) * 5;
#pragma unroll
        for (int c = 0; c < 5; c++) acc[c] = fmaf(xn, wrow[c], acc[c]);
    }
#pragma unroll
    for (int off = 16; off; off >>= 1)
#pragma unroll
        for (int c = 0; c < 5; c++)
            acc[c] += __shfl_xor_sync(0xFFFFFFFFu, acc[c], off);
    if (lane < 5) red[wid][lane] = acc[lane];
    __syncthreads();
    if (wid == 0 && lane < 5) {
        float t = 0.f;
#pragma unroll
        for (int w = 0; w < 8; w++) t += red[w][lane];
        out[s * 5 + lane] = t + out_b[lane];
    }
}

// ==============================================================================
extern "C" void kernel_launch(void* const* d_in, const int* in_sizes, int n_in,
                              void* d_out, int out_size)
{
    const float* X = (const float*)d_in[0];
    W9 ws; B9 bs;
    for (int t = 0; t < 3; t++)
        for (int m = 0; m < 3; m++) {
            ws.w[t*3+m] = (const float*)d_in[1 + t*6 + m*2];
            bs.b[t*3+m] = (const float*)d_in[2 + t*6 + m*2];
        }
    const float* fc_w  = (const float*)d_in[19];
    const float* fc_b  = (const float*)d_in[20];
    const float* ln_g  = (const float*)d_in[21];
    const float* ln_b  = (const float*)d_in[22];
    const float* out_w = (const float*)d_in[23];
    const float* out_b = (const float*)d_in[24];
    float* out = (float*)d_out;

    static int smem_set = 0;
    if (!smem_set) {
        cudaFuncSetAttribute(qkv_gemm_kernel, cudaFuncAttributeMaxDynamicSharedMemorySize, SMEM_GEMM);
        cudaFuncSetAttribute(fc_gemm_kernel,  cudaFuncAttributeMaxDynamicSharedMemorySize, SMEM_GEMM);
        smem_set = 1;
    }

    init_min_kernel<<<1, 1>>>();                    // idx 0
    conv_x_kernel<<<dim3(6, BSZ), 256>>>(X);        // idx 1
    conv_w_kernel<<<dim3(1024, 1, 9), 256>>>(ws);   // idx 2

    qkv_gemm_kernel<<<dim3(2, BSZ/128, 9), 256, SMEM_GEMM>>>(bs);  // idx 3 -> ncu target

    conv_fcw_kernel<<<128, 256>>>(fc_w);            // idx 4

    attn_logits_kernel<<<(BSZ*8)/256, 256>>>();
    attn_softmax_o_kernel<<<(BSZ*8)/256, 256>>>();

    fc_gemm_kernel<<<dim3(2, NROWS/128, 1), 256, SMEM_GEMM>>>(fc_b);

    ln_out_kernel<<<BSZ, 256>>>(ln_g, ln_b, out_w, out_b, out);
}